// round 12
// baseline (speedup 1.0000x reference)
#include <cuda_runtime.h>
#include <cuda_fp16.h>
#include <cstdint>
#include <cstddef>

#define Bv 16
#define Tv 576
#define NHv 12
#define HDv 64
#define DMv 768
#define LDv 256

// ---------------- scratch (static device allocations; no cudaMalloc) ---------
__device__ __half g_qh[Bv * Tv * DMv];
__device__ __half g_lath[Bv * Tv * LDv];
__device__ __half g_lp2h[Bv * 144 * LDv];
__device__ __half g_lp4h[Bv * 36 * LDv];
__device__ __half g_kh[Bv * Tv * DMv];
__device__ __half g_vh[Bv * Tv * DMv];
__device__ __half g_k2h[Bv * 144 * DMv];
__device__ __half g_v2h[Bv * 144 * DMv];
__device__ __half g_k4h[Bv * 36 * DMv];
__device__ __half g_v4h[Bv * 36 * DMv];
__device__ float g_ctx[Bv * Tv * DMv];
__device__ __half g_ctxh[Bv * Tv * DMv];
__device__ __half g_wch[2555904];        // fp16 weights
__device__ __half g_xh[Bv * Tv * DMv];   // fp16 x

// ---------------- helpers -----------------------------------------------------
__device__ __forceinline__ uint32_t pack_f16x2(float lo, float hi) {
    uint32_t u;
    asm("cvt.rn.f16x2.f32 %0, %1, %2;" : "=r"(u) : "f"(hi), "f"(lo));
    return u;
}

__device__ __forceinline__ void mma_f16(float& c0, float& c1, float& c2, float& c3,
                                        uint32_t a0, uint32_t a1, uint32_t a2, uint32_t a3,
                                        uint32_t b0, uint32_t b1) {
    asm volatile(
        "mma.sync.aligned.m16n8k16.row.col.f32.f16.f16.f32 "
        "{%0,%1,%2,%3}, {%4,%5,%6,%7}, {%8,%9}, {%0,%1,%2,%3};"
        : "+f"(c0), "+f"(c1), "+f"(c2), "+f"(c3)
        : "r"(a0), "r"(a1), "r"(a2), "r"(a3), "r"(b0), "r"(b1));
}

__device__ __forceinline__ void ldsm4(uint32_t& r0, uint32_t& r1, uint32_t& r2,
                                      uint32_t& r3, uint32_t addr) {
    asm volatile("ldmatrix.sync.aligned.m8n8.x4.shared.b16 {%0,%1,%2,%3}, [%4];"
                 : "=r"(r0), "=r"(r1), "=r"(r2), "=r"(r3) : "r"(addr));
}
__device__ __forceinline__ void ldsm4t(uint32_t& r0, uint32_t& r1, uint32_t& r2,
                                       uint32_t& r3, uint32_t addr) {
    asm volatile("ldmatrix.sync.aligned.m8n8.x4.trans.shared.b16 {%0,%1,%2,%3}, [%4];"
                 : "=r"(r0), "=r"(r1), "=r"(r2), "=r"(r3) : "r"(addr));
}

__device__ __forceinline__ void cpa16(uint32_t dst, const void* src) {
    asm volatile("cp.async.cg.shared.global [%0], [%1], 16;" :: "r"(dst), "l"(src));
}
__device__ __forceinline__ void cpa16z(uint32_t dst, const void* src, int pred) {
    asm volatile(
        "{\n\t.reg .pred p;\n\tsetp.ne.b32 p, %2, 0;\n\t"
        "@p cp.async.cg.shared.global [%0], [%1], 16;\n\t"
        "@!p cp.async.cg.shared.global [%0], [%1], 16, 0;\n\t}"
        :: "r"(dst), "l"(src), "r"(pred));
}
__device__ __forceinline__ void cp_commit() { asm volatile("cp.async.commit_group;"); }
__device__ __forceinline__ void cp_wait0() { asm volatile("cp.async.wait_group 0;"); }
__device__ __forceinline__ void cp_wait1() { asm volatile("cp.async.wait_group 1;"); }

// ---------------- fp16 pre-conversion, vectorized ------------------------------
struct CvtArgs {
    const float* src[10];
    __half* dst[10];
    int n4[10];
};
__global__ void cvtw_kernel(CvtArgs a) {
    int gid = blockIdx.x * blockDim.x + threadIdx.x;
    int stride = gridDim.x * blockDim.x;
#pragma unroll
    for (int s = 0; s < 10; s++) {
        const float4* sp = (const float4*)a.src[s];
        uint2* dp = (uint2*)a.dst[s];
        int n = a.n4[s];
        for (int i = gid; i < n; i += stride) {
            float4 v = sp[i];
            uint2 o;
            o.x = pack_f16x2(v.x, v.y);
            o.y = pack_f16x2(v.z, v.w);
            dp[i] = o;
        }
    }
}

// ---------------- fp16 tensor-core GEMM, 3-stage cp.async, 256x128, BK=64 ------
// C(/C2) = A(MxK) * Bw(KxN) (+bias). fp16 in, fp32 accum. 512 threads,
// 16 warps (4 wm x 4 wn), warp tile 64x32.
// smem words: A 3 x 9216 at 0 (row stride 36); B 3 x 4352 at 27648 (stride 68).
// Total 40704 words = 162,816 B (1 CTA/SM, 16 warps).
__global__ __launch_bounds__(512, 1) void gemm_fp16(
    const __half* __restrict__ A, const __half* __restrict__ Bw,
    const __half* __restrict__ B2, const float* __restrict__ bias,
    void* __restrict__ Cv, void* __restrict__ C2v,
    int M, int N, int K, int fp16out) {
    if (blockIdx.z == 1) { Bw = B2; Cv = C2v; }

    extern __shared__ uint32_t sm[];
    const int bm = blockIdx.y * 256;
    const int bn = blockIdx.x * 128;
    const int tid = threadIdx.x;
    const int lane = tid & 31;
    const int warp = tid >> 5;
    const int wm = (warp & 3) * 64;
    const int wn = (warp >> 2) * 32;
    const int g = lane >> 2;
    const int t = lane & 3;
    const int nk = K >> 6;
    uint32_t sb = (uint32_t)__cvta_generic_to_shared(sm);

    auto issue = [&](int it) {
        int buf = it % 3;
        int k0 = it << 6;
        // A: 256 rows x 64 halves = 2048 16B-chunks, 4 per thread
#pragma unroll
        for (int u = 0; u < 4; u++) {
            int idx = u * 512 + tid;
            int r = idx >> 3;
            int ch = idx & 7;
            int pred = (bm + r) < M;
            cpa16z(sb + (buf * 9216 + r * 36 + ch * 4) * 4,
                   A + (size_t)(bm + r) * K + k0 + ch * 8, pred);
        }
        // B: 64 rows x 128 halves = 1024 chunks, 2 per thread
#pragma unroll
        for (int u = 0; u < 2; u++) {
            int idx = u * 512 + tid;
            int kk = idx >> 4;
            int ch = idx & 15;
            cpa16(sb + (27648 + buf * 4352 + kk * 68 + ch * 4) * 4,
                  Bw + (size_t)(k0 + kk) * N + bn + ch * 8);
        }
        cp_commit();
    };

    float c[4][4][4];
#pragma unroll
    for (int mt = 0; mt < 4; mt++)
#pragma unroll
        for (int nt = 0; nt < 4; nt++)
#pragma unroll
            for (int r = 0; r < 4; r++) c[mt][nt][r] = 0.f;

    issue(0);
    issue(1);

    const uint32_t aB = sb + (((wm + (lane & 15)) * 36) + (lane >> 4) * 4) * 4;
    const uint32_t bB = sb + 27648 * 4 +
        (((((lane >> 3) & 1) * 8 + (lane & 7)) * 68) + (wn >> 1) + (lane >> 4) * 4) * 4;

    for (int it = 0; it < nk; it++) {
        if (it + 1 < nk) cp_wait1(); else cp_wait0();
        __syncthreads();
        if (it + 2 < nk) issue(it + 2);
        const uint32_t aOff = (uint32_t)((it % 3) * 9216 * 4);
        const uint32_t bOff = (uint32_t)((it % 3) * 4352 * 4);
#pragma unroll
        for (int ks = 0; ks < 4; ks++) {
            uint32_t af[4][4];
#pragma unroll
            for (int mt = 0; mt < 4; mt++)
                ldsm4(af[mt][0], af[mt][1], af[mt][2], af[mt][3],
                      aB + aOff + (uint32_t)((mt * 16 * 36 + ks * 8) * 4));
            uint32_t bf[4][2];
#pragma unroll
            for (int nh = 0; nh < 2; nh++) {
                uint32_t v0, v1, v2, v3;
                ldsm4t(v0, v1, v2, v3,
                       bB + bOff + (uint32_t)((ks * 16 * 68 + nh * 8) * 4));
                bf[nh * 2][0] = v0; bf[nh * 2][1] = v1;
                bf[nh * 2 + 1][0] = v2; bf[nh * 2 + 1][1] = v3;
            }
#pragma unroll
            for (int mt = 0; mt < 4; mt++)
#pragma unroll
                for (int nt = 0; nt < 4; nt++)
                    mma_f16(c[mt][nt][0], c[mt][nt][1], c[mt][nt][2], c[mt][nt][3],
                            af[mt][0], af[mt][1], af[mt][2], af[mt][3],
                            bf[nt][0], bf[nt][1]);
        }
        __syncthreads();
    }

#pragma unroll
    for (int mt = 0; mt < 4; mt++) {
#pragma unroll
        for (int nt = 0; nt < 4; nt++) {
            int row0 = bm + wm + mt * 16 + g;
            int col = bn + wn + nt * 8 + t * 2;
            if (fp16out) {
                __half* Ch = (__half*)Cv;
                uint32_t h01 = pack_f16x2(c[mt][nt][0], c[mt][nt][1]);
                uint32_t h23 = pack_f16x2(c[mt][nt][2], c[mt][nt][3]);
                if (row0 < M) *(uint32_t*)(Ch + (size_t)row0 * N + col) = h01;
                if (row0 + 8 < M) *(uint32_t*)(Ch + (size_t)(row0 + 8) * N + col) = h23;
            } else {
                float* C = (float*)Cv;
                float b0 = bias ? bias[col] : 0.f;
                float b1 = bias ? bias[col + 1] : 0.f;
                if (row0 < M)
                    *(float2*)(C + (size_t)row0 * N + col) =
                        make_float2(c[mt][nt][0] + b0, c[mt][nt][1] + b1);
                if (row0 + 8 < M)
                    *(float2*)(C + (size_t)(row0 + 8) * N + col) =
                        make_float2(c[mt][nt][2] + b0, c[mt][nt][3] + b1);
            }
        }
    }
}

// ---------------- exact sxs mean pooling (fp16 in/out, fp32 sum) ---------------
__global__ void pool_kernel(const __half* __restrict__ lat, __half* __restrict__ out,
                            int s, int g, int n) {
    int idx = blockIdx.x * blockDim.x + threadIdx.x;
    if (idx >= n) return;
    int c = idx & (LDv - 1);
    int rest = idx >> 8;
    int cell = rest % (g * g);
    int b = rest / (g * g);
    int gh = cell / g, gw = cell % g;
    float sum = 0.f;
    for (int i = 0; i < s; i++)
        for (int j = 0; j < s; j++)
            sum += __half2float(
                lat[((size_t)(b * Tv) + (gh * s + i) * 24 + (gw * s + j)) * LDv + c]);
    out[idx] = __float2half(sum / (float)(s * s));
}

// ---------------- fused 3-scale fp16 flash attention ---------------------------
// s=1 fast path (separable integer bias). Final segment writes ctxh (fp16)
// directly, folding the old cvtctx kernel into the epilogue.
#define ATT_SMEM_WORDS 14080

__global__ __launch_bounds__(256, 2) void attn_fused(
    const __half* __restrict__ qbuf,
    const __half* __restrict__ k1, const __half* __restrict__ v1,
    const __half* __restrict__ k2, const __half* __restrict__ v2,
    const __half* __restrict__ k4, const __half* __restrict__ v4,
    const float* __restrict__ tbl1, const float* __restrict__ tbl2,
    const float* __restrict__ tbl4, float* __restrict__ ctx,
    __half* __restrict__ ctxh) {
    extern __shared__ uint32_t smu[];
    float* khcs = (float*)(smu + 13824);
    float* kwcs = khcs + 128;
    int* ibase = (int*)khcs;
    uint32_t sb = (uint32_t)__cvta_generic_to_shared(smu);

    const int b = blockIdx.z;
    const int h = blockIdx.y;
    const int q0 = blockIdx.x * 128;
    const int tid = threadIdx.x;
    const int lane = tid & 31;
    const int w = tid >> 5;
    const int g = lane >> 2;
    const int t = lane & 3;
    const int lr0 = w * 16 + g;
    const int lr1 = lr0 + 8;

    auto issue_kv = [&](int vt) {
        const __half *kb, *vb;
        int Kt, kt;
        if (vt < 9) {
            kb = k1 + (size_t)b * 576 * DMv + h * HDv;
            vb = v1 + (size_t)b * 576 * DMv + h * HDv;
            Kt = 576; kt = vt;
        } else if (vt < 12) {
            kb = k2 + (size_t)b * 144 * DMv + h * HDv;
            vb = v2 + (size_t)b * 144 * DMv + h * HDv;
            Kt = 144; kt = vt - 9;
        } else {
            kb = k4 + (size_t)b * 36 * DMv + h * HDv;
            vb = v4 + (size_t)b * 36 * DMv + h * HDv;
            Kt = 36; kt = 0;
        }
        int buf = vt & 1;
#pragma unroll
        for (int u = 0; u < 2; u++) {
            int idx = u * 256 + tid;
            int r = idx >> 3;
            int c8 = (idx & 7) << 3;
            int kg = kt * 64 + r;
            int pred = kg < Kt;
            cpa16z(sb + (buf * 2304 + r * 36 + (c8 >> 1)) * 4,
                   kb + (size_t)kg * DMv + c8, pred);
            cpa16z(sb + (4608 + buf * 2304 + r * 36 + (c8 >> 1)) * 4,
                   vb + (size_t)kg * DMv + c8, pred);
        }
    };

    const __half* qsrc = qbuf + (size_t)(b * Tv) * DMv + h * HDv;
#pragma unroll
    for (int u = 0; u < 4; u++) {
        int idx = u * 256 + tid;
        int r = idx >> 3;
        int c8 = (idx & 7) << 3;
        int row = q0 + r;
        if (row > Tv - 1) row = Tv - 1;
        *(uint4*)&smu[9216 + r * 36 + (c8 >> 1)] =
            *(const uint4*)(qsrc + (size_t)row * DMv + c8);
    }
    issue_kv(0);
    cp_commit();
    __syncthreads();

    uint32_t qf[4][4];
#pragma unroll
    for (int ks = 0; ks < 4; ks++) {
        qf[ks][0] = smu[9216 + lr0 * 36 + ks * 8 + t];
        qf[ks][1] = smu[9216 + lr1 * 36 + ks * 8 + t];
        qf[ks][2] = smu[9216 + lr0 * 36 + ks * 8 + t + 4];
        qf[ks][3] = smu[9216 + lr1 * 36 + ks * 8 + t + 4];
    }

    float o[8][4];
#pragma unroll
    for (int nt = 0; nt < 8; nt++)
#pragma unroll
        for (int r = 0; r < 4; r++) o[nt][r] = 0.f;
    float l0 = 0.f, l1 = 0.f;

    const float scl = 0.125f;
    const int qi0 = q0 + lr0;
    const int qi1 = q0 + lr1;
    const int qc0 = qi0 < Tv ? qi0 : Tv - 1;
    const int qc1 = qi1 < Tv ? qi1 : Tv - 1;
    const int qh0i = qc0 / 24, qw0i = qc0 % 24;
    const int qh1i = qc1 / 24, qw1i = qc1 % 24;
    const int qoff0 = qh0i * 47 + qw0i;
    const int qoff1 = qh1i * 47 + qw1i;
    const float qh0 = (float)qh0i, qw0 = (float)qw0i;
    const float qh1 = (float)qh1i, qw1 = (float)qw1i;
    float* c0p = ctx + ((size_t)(b * Tv + qc0)) * DMv + h * HDv;
    float* c1p = ctx + ((size_t)(b * Tv + qc1)) * DMv + h * HDv;
    __half* c0ph = ctxh + ((size_t)(b * Tv + qc0)) * DMv + h * HDv;
    __half* c1ph = ctxh + ((size_t)(b * Tv + qc1)) * DMv + h * HDv;

    const uint32_t krow = sb + (((lane & 7) * 36) + ((lane >> 3) << 2)) * 4;
    const uint32_t vrow = sb + 4608 * 4 +
        (((((lane >> 3) & 1) * 8 + (lane & 7)) * 36) + ((lane >> 4) << 2)) * 4;

    for (int vt = 0; vt < 13; vt++) {
        int Kt, kt, gw_, s_, tw_;
        const float* tb;
        if (vt < 9)       { Kt = 576; kt = vt;      gw_ = 24; s_ = 1; tw_ = 47; tb = tbl1 + h * (47 * 47); }
        else if (vt < 12) { Kt = 144; kt = vt - 9;  gw_ = 12; s_ = 2; tw_ = 23; tb = tbl2 + h * (47 * 23); }
        else              { Kt = 36;  kt = 0;       gw_ = 6;  s_ = 4; tw_ = 11; tb = tbl4 + h * (47 * 11); }
        const float hctr = 0.5f * (float)(s_ - 1);
        const int buf = vt & 1;

        cp_wait0();
        if (tid < 64) {
            int kg = kt * 64 + tid;
            if (vt < 9) {
                ibase[buf * 64 + tid] = (23 - kg / 24) * 47 + (23 - kg % 24);
            } else if (kg < Kt) {
                khcs[buf * 64 + tid] = (float)((kg / gw_) * s_) + hctr;
                kwcs[buf * 64 + tid] = (float)((kg % gw_) * s_) + hctr;
            }
        }
        __syncthreads();
        if (vt + 1 < 13) { issue_kv(vt + 1); cp_commit(); }

        const uint32_t kbase = krow + (buf * 2304) * 4;
        const uint32_t vbase = vrow + (buf * 2304) * 4;

        uint32_t pA[8], pB[8];
        if (vt < 9) {
            const int* ib = ibase + buf * 64;
#pragma unroll
            for (int nt = 0; nt < 8; nt++) {
                uint32_t r0, r1, r2, r3, r4, r5, r6, r7;
                ldsm4(r0, r1, r2, r3, kbase + (nt * 8 * 36) * 4);
                ldsm4(r4, r5, r6, r7, kbase + (nt * 8 * 36) * 4 + 64);
                float s0 = 0.f, s1 = 0.f, s2 = 0.f, s3 = 0.f;
                mma_f16(s0, s1, s2, s3, qf[0][0], qf[0][1], qf[0][2], qf[0][3], r0, r1);
                mma_f16(s0, s1, s2, s3, qf[1][0], qf[1][1], qf[1][2], qf[1][3], r2, r3);
                mma_f16(s0, s1, s2, s3, qf[2][0], qf[2][1], qf[2][2], qf[2][3], r4, r5);
                mma_f16(s0, s1, s2, s3, qf[3][0], qf[3][1], qf[3][2], qf[3][3], r6, r7);

                int lc = nt * 8 + t * 2;
                int bA = ib[lc], bB = ib[lc + 1];
                float p0 = __expf(s0 * scl + __ldg(tb + bA + qoff0));
                float p1 = __expf(s1 * scl + __ldg(tb + bB + qoff0));
                float p2 = __expf(s2 * scl + __ldg(tb + bA + qoff1));
                float p3 = __expf(s3 * scl + __ldg(tb + bB + qoff1));
                l0 += p0 + p1;
                l1 += p2 + p3;
                pA[nt] = pack_f16x2(p0, p1);
                pB[nt] = pack_f16x2(p2, p3);
            }
        } else {
#pragma unroll
            for (int nt = 0; nt < 8; nt++) {
                uint32_t r0, r1, r2, r3, r4, r5, r6, r7;
                ldsm4(r0, r1, r2, r3, kbase + (nt * 8 * 36) * 4);
                ldsm4(r4, r5, r6, r7, kbase + (nt * 8 * 36) * 4 + 64);
                float s0 = 0.f, s1 = 0.f, s2 = 0.f, s3 = 0.f;
                mma_f16(s0, s1, s2, s3, qf[0][0], qf[0][1], qf[0][2], qf[0][3], r0, r1);
                mma_f16(s0, s1, s2, s3, qf[1][0], qf[1][1], qf[1][2], qf[1][3], r2, r3);
                mma_f16(s0, s1, s2, s3, qf[2][0], qf[2][1], qf[2][2], qf[2][3], r4, r5);
                mma_f16(s0, s1, s2, s3, qf[3][0], qf[3][1], qf[3][2], qf[3][3], r6, r7);

                int lc = nt * 8 + t * 2;
                int kg = kt * 64 + lc;
                float p0 = 0.f, p1 = 0.f, p2 = 0.f, p3 = 0.f;
                if (kg < Kt) {
                    float khcA = khcs[buf * 64 + lc], kwcA = kwcs[buf * 64 + lc];
                    float khcB = khcs[buf * 64 + lc + 1], kwcB = kwcs[buf * 64 + lc + 1];
                    int rh0a = (int)(qh0 - khcA) + 23, rw0a = (int)(qw0 - kwcA) + (gw_ - 1);
                    int rh0b = (int)(qh0 - khcB) + 23, rw0b = (int)(qw0 - kwcB) + (gw_ - 1);
                    int rh1a = (int)(qh1 - khcA) + 23, rw1a = (int)(qw1 - kwcA) + (gw_ - 1);
                    int rh1b = (int)(qh1 - khcB) + 23, rw1b = (int)(qw1 - kwcB) + (gw_ - 1);
                    p0 = __expf(s0 * scl + __ldg(&tb[rh0a * tw_ + rw0a]));
                    p1 = __expf(s1 * scl + __ldg(&tb[rh0b * tw_ + rw0b]));
                    p2 = __expf(s2 * scl + __ldg(&tb[rh1a * tw_ + rw1a]));
                    p3 = __expf(s3 * scl + __ldg(&tb[rh1b * tw_ + rw1b]));
                }
                l0 += p0 + p1;
                l1 += p2 + p3;
                pA[nt] = pack_f16x2(p0, p1);
                pB[nt] = pack_f16x2(p2, p3);
            }
        }

#pragma unroll
        for (int ks = 0; ks < 4; ks++) {
            uint32_t a0 = pA[2 * ks], a1 = pB[2 * ks];
            uint32_t a2 = pA[2 * ks + 1], a3 = pB[2 * ks + 1];
#pragma unroll
            for (int p = 0; p < 4; p++) {
                uint32_t v0, v1, v2, v3;
                ldsm4t(v0, v1, v2, v3, vbase + (ks * 16 * 36 + p * 8) * 4);
                mma_f16(o[2 * p][0], o[2 * p][1], o[2 * p][2], o[2 * p][3],
                        a0, a1, a2, a3, v0, v1);
                mma_f16(o[2 * p + 1][0], o[2 * p + 1][1], o[2 * p + 1][2], o[2 * p + 1][3],
                        a0, a1, a2, a3, v2, v3);
            }
        }

        if (vt == 8 || vt == 11 || vt == 12) {
            float L0 = l0, L1 = l1;
            L0 += __shfl_xor_sync(0xffffffffu, L0, 1);
            L0 += __shfl_xor_sync(0xffffffffu, L0, 2);
            L1 += __shfl_xor_sync(0xffffffffu, L1, 1);
            L1 += __shfl_xor_sync(0xffffffffu, L1, 2);
            float inv0 = 1.f / (3.f * L0);
            float inv1 = 1.f / (3.f * L1);
            if (vt == 8) {
#pragma unroll
                for (int nt = 0; nt < 8; nt++) {
                    int col = nt * 8 + t * 2;
                    if (qi0 < Tv) {
                        c0p[col] = o[nt][0] * inv0;
                        c0p[col + 1] = o[nt][1] * inv0;
                    }
                    if (qi1 < Tv) {
                        c1p[col] = o[nt][2] * inv1;
                        c1p[col + 1] = o[nt][3] * inv1;
                    }
                }
            } else if (vt == 11) {
#pragma unroll
                for (int nt = 0; nt < 8; nt++) {
                    int col = nt * 8 + t * 2;
                    if (qi0 < Tv) {
                        c0p[col] += o[nt][0] * inv0;
                        c0p[col + 1] += o[nt][1] * inv0;
                    }
                    if (qi1 < Tv) {
                        c1p[col] += o[nt][2] * inv1;
                        c1p[col + 1] += o[nt][3] * inv1;
                    }
                }
            } else {
                // final: read fp32 partial, add, convert to fp16 for the
                // out-projection (replaces the old cvtctx kernel)
#pragma unroll
                for (int nt = 0; nt < 8; nt++) {
                    int col = nt * 8 + t * 2;
                    if (qi0 < Tv) {
                        float v0 = c0p[col] + o[nt][0] * inv0;
                        float v1 = c0p[col + 1] + o[nt][1] * inv0;
                        *(uint32_t*)(c0ph + col) = pack_f16x2(v0, v1);
                    }
                    if (qi1 < Tv) {
                        float v2 = c1p[col] + o[nt][2] * inv1;
                        float v3 = c1p[col + 1] + o[nt][3] * inv1;
                        *(uint32_t*)(c1ph + col) = pack_f16x2(v2, v3);
                    }
                }
            }
#pragma unroll
            for (int nt = 0; nt < 8; nt++)
#pragma unroll
                for (int r = 0; r < 4; r++) o[nt][r] = 0.f;
            l0 = 0.f;
            l1 = 0.f;
        }
    }
}

// ---------------- launch ------------------------------------------------------
extern "C" void kernel_launch(void* const* d_in, const int* in_sizes, int n_in,
                              void* d_out, int out_size) {
    const float* x    = (const float*)d_in[0];
    const float* wq   = (const float*)d_in[1];
    const float* wdkv = (const float*)d_in[2];
    const float* wuk1 = (const float*)d_in[3];
    const float* wuk2 = (const float*)d_in[4];
    const float* wuk4 = (const float*)d_in[5];
    const float* wuv1 = (const float*)d_in[6];
    const float* wuv2 = (const float*)d_in[7];
    const float* wuv4 = (const float*)d_in[8];
    const float* wout = (const float*)d_in[9];
    const float* bout = (const float*)d_in[10];
    const float* tbl1 = (const float*)d_in[11];
    const float* tbl2 = (const float*)d_in[12];
    const float* tbl4 = (const float*)d_in[13];

    float* ctx;
    __half *qh, *lath, *lp2h, *lp4h, *kh, *vh, *k2h, *v2h, *k4h, *v4h, *wch, *xh, *ctxh;
    cudaGetSymbolAddress((void**)&qh, g_qh);
    cudaGetSymbolAddress((void**)&lath, g_lath);
    cudaGetSymbolAddress((void**)&lp2h, g_lp2h);
    cudaGetSymbolAddress((void**)&lp4h, g_lp4h);
    cudaGetSymbolAddress((void**)&kh, g_kh);
    cudaGetSymbolAddress((void**)&vh, g_vh);
    cudaGetSymbolAddress((void**)&k2h, g_k2h);
    cudaGetSymbolAddress((void**)&v2h, g_v2h);
    cudaGetSymbolAddress((void**)&k4h, g_k4h);
    cudaGetSymbolAddress((void**)&v4h, g_v4h);
    cudaGetSymbolAddress((void**)&ctx, g_ctx);
    cudaGetSymbolAddress((void**)&ctxh, g_ctxh);
    cudaGetSymbolAddress((void**)&wch, g_wch);
    cudaGetSymbolAddress((void**)&xh, g_xh);

    const int O_WQ = 0, O_WDKV = 589824, O_WUK1 = 786432, O_WUV1 = 983040;
    const int O_WUK2 = 1179648, O_WUV2 = 1376256, O_WUK4 = 1572864, O_WUV4 = 1769472;
    const int O_WOUT = 1966080;

    CvtArgs ca;
    ca.src[0] = wq;   ca.dst[0] = wch + O_WQ;   ca.n4[0] = 589824 / 4;
    ca.src[1] = wdkv; ca.dst[1] = wch + O_WDKV; ca.n4[1] = 196608 / 4;
    ca.src[2] = wuk1; ca.dst[2] = wch + O_WUK1; ca.n4[2] = 196608 / 4;
    ca.src[3] = wuv1; ca.dst[3] = wch + O_WUV1; ca.n4[3] = 196608 / 4;
    ca.src[4] = wuk2; ca.dst[4] = wch + O_WUK2; ca.n4[4] = 196608 / 4;
    ca.src[5] = wuv2; ca.dst[5] = wch + O_WUV2; ca.n4[5] = 196608 / 4;
    ca.src[6] = wuk4; ca.dst[6] = wch + O_WUK4; ca.n4[6] = 196608 / 4;
    ca.src[7] = wuv4; ca.dst[7] = wch + O_WUV4; ca.n4[7] = 196608 / 4;
    ca.src[8] = wout; ca.dst[8] = wch + O_WOUT; ca.n4[8] = 589824 / 4;
    ca.src[9] = x;    ca.dst[9] = xh;           ca.n4[9] = Bv * Tv * DMv / 4;

    const int GEMM_SMEM = 40704 * 4;           // 162,816 B
    const int ATT_SMEM = ATT_SMEM_WORDS * 4;   // 56,320 B
    cudaFuncSetAttribute(gemm_fp16, cudaFuncAttributeMaxDynamicSharedMemorySize,
                         GEMM_SMEM);
    cudaFuncSetAttribute(attn_fused, cudaFuncAttributeMaxDynamicSharedMemorySize,
                         ATT_SMEM);

    const int MQ = Bv * Tv;  // 9216

    cvtw_kernel<<<512, 256>>>(ca);

    gemm_fp16<<<dim3(6, 36), 512, GEMM_SMEM>>>(xh, wch + O_WQ, nullptr, nullptr,
                                               qh, nullptr, MQ, DMv, DMv, 1);
    gemm_fp16<<<dim3(2, 36), 512, GEMM_SMEM>>>(xh, wch + O_WDKV, nullptr, nullptr,
                                               lath, nullptr, MQ, LDv, DMv, 1);

    gemm_fp16<<<dim3(6, 36, 2), 512, GEMM_SMEM>>>(lath, wch + O_WUK1, wch + O_WUV1,
                                                  nullptr, kh, vh, MQ, DMv, LDv, 1);

    pool_kernel<<<(Bv * 144 * LDv + 255) / 256, 256>>>(lath, lp2h, 2, 12, Bv * 144 * LDv);
    gemm_fp16<<<dim3(6, 9, 2), 512, GEMM_SMEM>>>(lp2h, wch + O_WUK2, wch + O_WUV2,
                                                 nullptr, k2h, v2h, Bv * 144, DMv, LDv, 1);

    pool_kernel<<<(Bv * 36 * LDv + 255) / 256, 256>>>(lath, lp4h, 4, 6, Bv * 36 * LDv);
    gemm_fp16<<<dim3(6, 3, 2), 512, GEMM_SMEM>>>(lp4h, wch + O_WUK4, wch + O_WUV4,
                                                 nullptr, k4h, v4h, Bv * 36, DMv, LDv, 1);

    attn_fused<<<dim3(5, NHv, Bv), 256, ATT_SMEM>>>(qh, kh, vh, k2h, v2h, k4h, v4h,
                                                    tbl1, tbl2, tbl4, ctx, ctxh);

    gemm_fp16<<<dim3(6, 36), 512, GEMM_SMEM>>>(ctxh, wch + O_WOUT, nullptr, bout,
                                               (float*)d_out, nullptr, MQ, DMv, DMv, 0);
}

// round 13
// speedup vs baseline: 1.1385x; 1.1385x over previous
#include <cuda_runtime.h>
#include <cuda_fp16.h>
#include <cstdint>
#include <cstddef>

#define Bv 16
#define Tv 576
#define NHv 12
#define HDv 64
#define DMv 768
#define LDv 256

// ---------------- scratch (static device allocations; no cudaMalloc) ---------
__device__ __half g_qh[Bv * Tv * DMv];
__device__ __half g_lath[Bv * Tv * LDv];
__device__ __half g_lp2h[Bv * 144 * LDv];
__device__ __half g_lp4h[Bv * 36 * LDv];
__device__ __half g_kh[Bv * Tv * DMv];
__device__ __half g_vh[Bv * Tv * DMv];
__device__ __half g_k2h[Bv * 144 * DMv];
__device__ __half g_v2h[Bv * 144 * DMv];
__device__ __half g_k4h[Bv * 36 * DMv];
__device__ __half g_v4h[Bv * 36 * DMv];
__device__ float g_ctx[Bv * Tv * DMv];
__device__ __half g_ctxh[Bv * Tv * DMv];
__device__ __half g_wch[2555904];        // fp16 weights
__device__ __half g_xh[Bv * Tv * DMv];   // fp16 x

// ---------------- helpers -----------------------------------------------------
__device__ __forceinline__ uint32_t pack_f16x2(float lo, float hi) {
    uint32_t u;
    asm("cvt.rn.f16x2.f32 %0, %1, %2;" : "=r"(u) : "f"(hi), "f"(lo));
    return u;
}

__device__ __forceinline__ void mma_f16(float& c0, float& c1, float& c2, float& c3,
                                        uint32_t a0, uint32_t a1, uint32_t a2, uint32_t a3,
                                        uint32_t b0, uint32_t b1) {
    asm volatile(
        "mma.sync.aligned.m16n8k16.row.col.f32.f16.f16.f32 "
        "{%0,%1,%2,%3}, {%4,%5,%6,%7}, {%8,%9}, {%0,%1,%2,%3};"
        : "+f"(c0), "+f"(c1), "+f"(c2), "+f"(c3)
        : "r"(a0), "r"(a1), "r"(a2), "r"(a3), "r"(b0), "r"(b1));
}

__device__ __forceinline__ void ldsm4(uint32_t& r0, uint32_t& r1, uint32_t& r2,
                                      uint32_t& r3, uint32_t addr) {
    asm volatile("ldmatrix.sync.aligned.m8n8.x4.shared.b16 {%0,%1,%2,%3}, [%4];"
                 : "=r"(r0), "=r"(r1), "=r"(r2), "=r"(r3) : "r"(addr));
}
__device__ __forceinline__ void ldsm4t(uint32_t& r0, uint32_t& r1, uint32_t& r2,
                                       uint32_t& r3, uint32_t addr) {
    asm volatile("ldmatrix.sync.aligned.m8n8.x4.trans.shared.b16 {%0,%1,%2,%3}, [%4];"
                 : "=r"(r0), "=r"(r1), "=r"(r2), "=r"(r3) : "r"(addr));
}

__device__ __forceinline__ void cpa16(uint32_t dst, const void* src) {
    asm volatile("cp.async.cg.shared.global [%0], [%1], 16;" :: "r"(dst), "l"(src));
}
__device__ __forceinline__ void cpa16z(uint32_t dst, const void* src, int pred) {
    asm volatile(
        "{\n\t.reg .pred p;\n\tsetp.ne.b32 p, %2, 0;\n\t"
        "@p cp.async.cg.shared.global [%0], [%1], 16;\n\t"
        "@!p cp.async.cg.shared.global [%0], [%1], 16, 0;\n\t}"
        :: "r"(dst), "l"(src), "r"(pred));
}
__device__ __forceinline__ void cp_commit() { asm volatile("cp.async.commit_group;"); }
__device__ __forceinline__ void cp_wait0() { asm volatile("cp.async.wait_group 0;"); }
__device__ __forceinline__ void cp_wait1() { asm volatile("cp.async.wait_group 1;"); }

// ---------------- fp16 pre-conversion, vectorized ------------------------------
struct CvtArgs {
    const float* src[10];
    __half* dst[10];
    int n4[10];
};
__global__ void cvtw_kernel(CvtArgs a) {
    int gid = blockIdx.x * blockDim.x + threadIdx.x;
    int stride = gridDim.x * blockDim.x;
#pragma unroll
    for (int s = 0; s < 10; s++) {
        const float4* sp = (const float4*)a.src[s];
        uint2* dp = (uint2*)a.dst[s];
        int n = a.n4[s];
        for (int i = gid; i < n; i += stride) {
            float4 v = sp[i];
            uint2 o;
            o.x = pack_f16x2(v.x, v.y);
            o.y = pack_f16x2(v.z, v.w);
            dp[i] = o;
        }
    }
}

// ---------------- fp16 tensor-core GEMM, multi-job, 3-stage, 128x128, BK=64 ----
// Up to 6 jobs per launch. Job selected by blockIdx.z when gridDim.z > 1,
// else by blockIdx.x >= xsplit (two-job x-concatenation).
// Core identical to the best 128x128/256-thread config (2 CTAs/SM).
struct GemmJobs {
    const __half* A[6];
    const __half* B[6];
    void* C[6];
    int M[6];
    int N[6];
    int fp16out[6];
};

__global__ __launch_bounds__(256, 2) void gemm_fp16(
    GemmJobs J, const float* __restrict__ bias, int K, int xsplit) {
    int job, bnIdx;
    if (gridDim.z > 1) {
        job = blockIdx.z;
        bnIdx = blockIdx.x;
    } else {
        job = (blockIdx.x >= xsplit) ? 1 : 0;
        bnIdx = job ? (blockIdx.x - xsplit) : blockIdx.x;
    }
    const __half* A = J.A[job];
    const __half* Bw = J.B[job];
    void* Cv = J.C[job];
    const int M = J.M[job];
    const int N = J.N[job];
    const int fp16out = J.fp16out[job];

    const int bm = blockIdx.y * 128;
    if (bm >= M) return;
    const int bn = bnIdx * 128;

    extern __shared__ uint32_t sm[];
    const int tid = threadIdx.x;
    const int lane = tid & 31;
    const int warp = tid >> 5;
    const int wm = (warp & 1) * 64;
    const int wn = (warp >> 1) * 32;
    const int g = lane >> 2;
    const int t = lane & 3;
    const int nk = K >> 6;
    uint32_t sb = (uint32_t)__cvta_generic_to_shared(sm);

    auto issue = [&](int it) {
        int buf = it % 3;
        int k0 = it << 6;
#pragma unroll
        for (int u = 0; u < 4; u++) {
            int idx = u * 256 + tid;
            int r = idx >> 3;
            int ch = idx & 7;
            int pred = (bm + r) < M;
            cpa16z(sb + (buf * 4608 + r * 36 + ch * 4) * 4,
                   A + (size_t)(bm + r) * K + k0 + ch * 8, pred);
        }
#pragma unroll
        for (int u = 0; u < 4; u++) {
            int idx = u * 256 + tid;
            int kk = idx >> 4;
            int ch = idx & 15;
            cpa16(sb + (13824 + buf * 4352 + kk * 68 + ch * 4) * 4,
                  Bw + (size_t)(k0 + kk) * N + bn + ch * 8);
        }
        cp_commit();
    };

    float c[4][4][4];
#pragma unroll
    for (int mt = 0; mt < 4; mt++)
#pragma unroll
        for (int nt = 0; nt < 4; nt++)
#pragma unroll
            for (int r = 0; r < 4; r++) c[mt][nt][r] = 0.f;

    issue(0);
    issue(1);

    const uint32_t aB = sb + (((wm + (lane & 15)) * 36) + (lane >> 4) * 4) * 4;
    const uint32_t bB = sb + 13824 * 4 +
        (((((lane >> 3) & 1) * 8 + (lane & 7)) * 68) + (wn >> 1) + (lane >> 4) * 4) * 4;

    for (int it = 0; it < nk; it++) {
        if (it + 1 < nk) cp_wait1(); else cp_wait0();
        __syncthreads();
        if (it + 2 < nk) issue(it + 2);
        const uint32_t aOff = (uint32_t)((it % 3) * 4608 * 4);
        const uint32_t bOff = (uint32_t)((it % 3) * 4352 * 4);
#pragma unroll
        for (int ks = 0; ks < 4; ks++) {
            uint32_t af[4][4];
#pragma unroll
            for (int mt = 0; mt < 4; mt++)
                ldsm4(af[mt][0], af[mt][1], af[mt][2], af[mt][3],
                      aB + aOff + (uint32_t)((mt * 16 * 36 + ks * 8) * 4));
            uint32_t bf[4][2];
#pragma unroll
            for (int nh = 0; nh < 2; nh++) {
                uint32_t v0, v1, v2, v3;
                ldsm4t(v0, v1, v2, v3,
                       bB + bOff + (uint32_t)((ks * 16 * 68 + nh * 8) * 4));
                bf[nh * 2][0] = v0; bf[nh * 2][1] = v1;
                bf[nh * 2 + 1][0] = v2; bf[nh * 2 + 1][1] = v3;
            }
#pragma unroll
            for (int mt = 0; mt < 4; mt++)
#pragma unroll
                for (int nt = 0; nt < 4; nt++)
                    mma_f16(c[mt][nt][0], c[mt][nt][1], c[mt][nt][2], c[mt][nt][3],
                            af[mt][0], af[mt][1], af[mt][2], af[mt][3],
                            bf[nt][0], bf[nt][1]);
        }
        __syncthreads();
    }

#pragma unroll
    for (int mt = 0; mt < 4; mt++) {
#pragma unroll
        for (int nt = 0; nt < 4; nt++) {
            int row0 = bm + wm + mt * 16 + g;
            int col = bn + wn + nt * 8 + t * 2;
            if (fp16out) {
                __half* Ch = (__half*)Cv;
                uint32_t h01 = pack_f16x2(c[mt][nt][0], c[mt][nt][1]);
                uint32_t h23 = pack_f16x2(c[mt][nt][2], c[mt][nt][3]);
                if (row0 < M) *(uint32_t*)(Ch + (size_t)row0 * N + col) = h01;
                if (row0 + 8 < M) *(uint32_t*)(Ch + (size_t)(row0 + 8) * N + col) = h23;
            } else {
                float* C = (float*)Cv;
                float b0 = bias ? bias[col] : 0.f;
                float b1 = bias ? bias[col + 1] : 0.f;
                if (row0 < M)
                    *(float2*)(C + (size_t)row0 * N + col) =
                        make_float2(c[mt][nt][0] + b0, c[mt][nt][1] + b1);
                if (row0 + 8 < M)
                    *(float2*)(C + (size_t)(row0 + 8) * N + col) =
                        make_float2(c[mt][nt][2] + b0, c[mt][nt][3] + b1);
            }
        }
    }
}

// ---------------- exact sxs mean pooling (fp16 in/out, fp32 sum) ---------------
__global__ void pool_kernel(const __half* __restrict__ lat, __half* __restrict__ out,
                            int s, int g, int n) {
    int idx = blockIdx.x * blockDim.x + threadIdx.x;
    if (idx >= n) return;
    int c = idx & (LDv - 1);
    int rest = idx >> 8;
    int cell = rest % (g * g);
    int b = rest / (g * g);
    int gh = cell / g, gw = cell % g;
    float sum = 0.f;
    for (int i = 0; i < s; i++)
        for (int j = 0; j < s; j++)
            sum += __half2float(
                lat[((size_t)(b * Tv) + (gh * s + i) * 24 + (gw * s + j)) * LDv + c]);
    out[idx] = __float2half(sum / (float)(s * s));
}

// ---------------- fused 3-scale fp16 flash attention ---------------------------
// s=1 fast path (separable integer bias); final segment writes ctxh directly.
#define ATT_SMEM_WORDS 14080

__global__ __launch_bounds__(256, 2) void attn_fused(
    const __half* __restrict__ qbuf,
    const __half* __restrict__ k1, const __half* __restrict__ v1,
    const __half* __restrict__ k2, const __half* __restrict__ v2,
    const __half* __restrict__ k4, const __half* __restrict__ v4,
    const float* __restrict__ tbl1, const float* __restrict__ tbl2,
    const float* __restrict__ tbl4, float* __restrict__ ctx,
    __half* __restrict__ ctxh) {
    extern __shared__ uint32_t smu[];
    float* khcs = (float*)(smu + 13824);
    float* kwcs = khcs + 128;
    int* ibase = (int*)khcs;
    uint32_t sb = (uint32_t)__cvta_generic_to_shared(smu);

    const int b = blockIdx.z;
    const int h = blockIdx.y;
    const int q0 = blockIdx.x * 128;
    const int tid = threadIdx.x;
    const int lane = tid & 31;
    const int w = tid >> 5;
    const int g = lane >> 2;
    const int t = lane & 3;
    const int lr0 = w * 16 + g;
    const int lr1 = lr0 + 8;

    auto issue_kv = [&](int vt) {
        const __half *kb, *vb;
        int Kt, kt;
        if (vt < 9) {
            kb = k1 + (size_t)b * 576 * DMv + h * HDv;
            vb = v1 + (size_t)b * 576 * DMv + h * HDv;
            Kt = 576; kt = vt;
        } else if (vt < 12) {
            kb = k2 + (size_t)b * 144 * DMv + h * HDv;
            vb = v2 + (size_t)b * 144 * DMv + h * HDv;
            Kt = 144; kt = vt - 9;
        } else {
            kb = k4 + (size_t)b * 36 * DMv + h * HDv;
            vb = v4 + (size_t)b * 36 * DMv + h * HDv;
            Kt = 36; kt = 0;
        }
        int buf = vt & 1;
#pragma unroll
        for (int u = 0; u < 2; u++) {
            int idx = u * 256 + tid;
            int r = idx >> 3;
            int c8 = (idx & 7) << 3;
            int kg = kt * 64 + r;
            int pred = kg < Kt;
            cpa16z(sb + (buf * 2304 + r * 36 + (c8 >> 1)) * 4,
                   kb + (size_t)kg * DMv + c8, pred);
            cpa16z(sb + (4608 + buf * 2304 + r * 36 + (c8 >> 1)) * 4,
                   vb + (size_t)kg * DMv + c8, pred);
        }
    };

    const __half* qsrc = qbuf + (size_t)(b * Tv) * DMv + h * HDv;
#pragma unroll
    for (int u = 0; u < 4; u++) {
        int idx = u * 256 + tid;
        int r = idx >> 3;
        int c8 = (idx & 7) << 3;
        int row = q0 + r;
        if (row > Tv - 1) row = Tv - 1;
        *(uint4*)&smu[9216 + r * 36 + (c8 >> 1)] =
            *(const uint4*)(qsrc + (size_t)row * DMv + c8);
    }
    issue_kv(0);
    cp_commit();
    __syncthreads();

    uint32_t qf[4][4];
#pragma unroll
    for (int ks = 0; ks < 4; ks++) {
        qf[ks][0] = smu[9216 + lr0 * 36 + ks * 8 + t];
        qf[ks][1] = smu[9216 + lr1 * 36 + ks * 8 + t];
        qf[ks][2] = smu[9216 + lr0 * 36 + ks * 8 + t + 4];
        qf[ks][3] = smu[9216 + lr1 * 36 + ks * 8 + t + 4];
    }

    float o[8][4];
#pragma unroll
    for (int nt = 0; nt < 8; nt++)
#pragma unroll
        for (int r = 0; r < 4; r++) o[nt][r] = 0.f;
    float l0 = 0.f, l1 = 0.f;

    const float scl = 0.125f;
    const int qi0 = q0 + lr0;
    const int qi1 = q0 + lr1;
    const int qc0 = qi0 < Tv ? qi0 : Tv - 1;
    const int qc1 = qi1 < Tv ? qi1 : Tv - 1;
    const int qh0i = qc0 / 24, qw0i = qc0 % 24;
    const int qh1i = qc1 / 24, qw1i = qc1 % 24;
    const int qoff0 = qh0i * 47 + qw0i;
    const int qoff1 = qh1i * 47 + qw1i;
    const float qh0 = (float)qh0i, qw0 = (float)qw0i;
    const float qh1 = (float)qh1i, qw1 = (float)qw1i;
    float* c0p = ctx + ((size_t)(b * Tv + qc0)) * DMv + h * HDv;
    float* c1p = ctx + ((size_t)(b * Tv + qc1)) * DMv + h * HDv;
    __half* c0ph = ctxh + ((size_t)(b * Tv + qc0)) * DMv + h * HDv;
    __half* c1ph = ctxh + ((size_t)(b * Tv + qc1)) * DMv + h * HDv;

    const uint32_t krow = sb + (((lane & 7) * 36) + ((lane >> 3) << 2)) * 4;
    const uint32_t vrow = sb + 4608 * 4 +
        (((((lane >> 3) & 1) * 8 + (lane & 7)) * 36) + ((lane >> 4) << 2)) * 4;

    for (int vt = 0; vt < 13; vt++) {
        int Kt, kt, gw_, s_, tw_;
        const float* tb;
        if (vt < 9)       { Kt = 576; kt = vt;      gw_ = 24; s_ = 1; tw_ = 47; tb = tbl1 + h * (47 * 47); }
        else if (vt < 12) { Kt = 144; kt = vt - 9;  gw_ = 12; s_ = 2; tw_ = 23; tb = tbl2 + h * (47 * 23); }
        else              { Kt = 36;  kt = 0;       gw_ = 6;  s_ = 4; tw_ = 11; tb = tbl4 + h * (47 * 11); }
        const float hctr = 0.5f * (float)(s_ - 1);
        const int buf = vt & 1;

        cp_wait0();
        if (tid < 64) {
            int kg = kt * 64 + tid;
            if (vt < 9) {
                ibase[buf * 64 + tid] = (23 - kg / 24) * 47 + (23 - kg % 24);
            } else if (kg < Kt) {
                khcs[buf * 64 + tid] = (float)((kg / gw_) * s_) + hctr;
                kwcs[buf * 64 + tid] = (float)((kg % gw_) * s_) + hctr;
            }
        }
        __syncthreads();
        if (vt + 1 < 13) { issue_kv(vt + 1); cp_commit(); }

        const uint32_t kbase = krow + (buf * 2304) * 4;
        const uint32_t vbase = vrow + (buf * 2304) * 4;

        uint32_t pA[8], pB[8];
        if (vt < 9) {
            const int* ib = ibase + buf * 64;
#pragma unroll
            for (int nt = 0; nt < 8; nt++) {
                uint32_t r0, r1, r2, r3, r4, r5, r6, r7;
                ldsm4(r0, r1, r2, r3, kbase + (nt * 8 * 36) * 4);
                ldsm4(r4, r5, r6, r7, kbase + (nt * 8 * 36) * 4 + 64);
                float s0 = 0.f, s1 = 0.f, s2 = 0.f, s3 = 0.f;
                mma_f16(s0, s1, s2, s3, qf[0][0], qf[0][1], qf[0][2], qf[0][3], r0, r1);
                mma_f16(s0, s1, s2, s3, qf[1][0], qf[1][1], qf[1][2], qf[1][3], r2, r3);
                mma_f16(s0, s1, s2, s3, qf[2][0], qf[2][1], qf[2][2], qf[2][3], r4, r5);
                mma_f16(s0, s1, s2, s3, qf[3][0], qf[3][1], qf[3][2], qf[3][3], r6, r7);

                int lc = nt * 8 + t * 2;
                int bA = ib[lc], bB2 = ib[lc + 1];
                float p0 = __expf(s0 * scl + __ldg(tb + bA + qoff0));
                float p1 = __expf(s1 * scl + __ldg(tb + bB2 + qoff0));
                float p2 = __expf(s2 * scl + __ldg(tb + bA + qoff1));
                float p3 = __expf(s3 * scl + __ldg(tb + bB2 + qoff1));
                l0 += p0 + p1;
                l1 += p2 + p3;
                pA[nt] = pack_f16x2(p0, p1);
                pB[nt] = pack_f16x2(p2, p3);
            }
        } else {
#pragma unroll
            for (int nt = 0; nt < 8; nt++) {
                uint32_t r0, r1, r2, r3, r4, r5, r6, r7;
                ldsm4(r0, r1, r2, r3, kbase + (nt * 8 * 36) * 4);
                ldsm4(r4, r5, r6, r7, kbase + (nt * 8 * 36) * 4 + 64);
                float s0 = 0.f, s1 = 0.f, s2 = 0.f, s3 = 0.f;
                mma_f16(s0, s1, s2, s3, qf[0][0], qf[0][1], qf[0][2], qf[0][3], r0, r1);
                mma_f16(s0, s1, s2, s3, qf[1][0], qf[1][1], qf[1][2], qf[1][3], r2, r3);
                mma_f16(s0, s1, s2, s3, qf[2][0], qf[2][1], qf[2][2], qf[2][3], r4, r5);
                mma_f16(s0, s1, s2, s3, qf[3][0], qf[3][1], qf[3][2], qf[3][3], r6, r7);

                int lc = nt * 8 + t * 2;
                int kg = kt * 64 + lc;
                float p0 = 0.f, p1 = 0.f, p2 = 0.f, p3 = 0.f;
                if (kg < Kt) {
                    float khcA = khcs[buf * 64 + lc], kwcA = kwcs[buf * 64 + lc];
                    float khcB = khcs[buf * 64 + lc + 1], kwcB = kwcs[buf * 64 + lc + 1];
                    int rh0a = (int)(qh0 - khcA) + 23, rw0a = (int)(qw0 - kwcA) + (gw_ - 1);
                    int rh0b = (int)(qh0 - khcB) + 23, rw0b = (int)(qw0 - kwcB) + (gw_ - 1);
                    int rh1a = (int)(qh1 - khcA) + 23, rw1a = (int)(qw1 - kwcA) + (gw_ - 1);
                    int rh1b = (int)(qh1 - khcB) + 23, rw1b = (int)(qw1 - kwcB) + (gw_ - 1);
                    p0 = __expf(s0 * scl + __ldg(&tb[rh0a * tw_ + rw0a]));
                    p1 = __expf(s1 * scl + __ldg(&tb[rh0b * tw_ + rw0b]));
                    p2 = __expf(s2 * scl + __ldg(&tb[rh1a * tw_ + rw1a]));
                    p3 = __expf(s3 * scl + __ldg(&tb[rh1b * tw_ + rw1b]));
                }
                l0 += p0 + p1;
                l1 += p2 + p3;
                pA[nt] = pack_f16x2(p0, p1);
                pB[nt] = pack_f16x2(p2, p3);
            }
        }

#pragma unroll
        for (int ks = 0; ks < 4; ks++) {
            uint32_t a0 = pA[2 * ks], a1 = pB[2 * ks];
            uint32_t a2 = pA[2 * ks + 1], a3 = pB[2 * ks + 1];
#pragma unroll
            for (int p = 0; p < 4; p++) {
                uint32_t v0, v1, v2, v3;
                ldsm4t(v0, v1, v2, v3, vbase + (ks * 16 * 36 + p * 8) * 4);
                mma_f16(o[2 * p][0], o[2 * p][1], o[2 * p][2], o[2 * p][3],
                        a0, a1, a2, a3, v0, v1);
                mma_f16(o[2 * p + 1][0], o[2 * p + 1][1], o[2 * p + 1][2], o[2 * p + 1][3],
                        a0, a1, a2, a3, v2, v3);
            }
        }

        if (vt == 8 || vt == 11 || vt == 12) {
            float L0 = l0, L1 = l1;
            L0 += __shfl_xor_sync(0xffffffffu, L0, 1);
            L0 += __shfl_xor_sync(0xffffffffu, L0, 2);
            L1 += __shfl_xor_sync(0xffffffffu, L1, 1);
            L1 += __shfl_xor_sync(0xffffffffu, L1, 2);
            float inv0 = 1.f / (3.f * L0);
            float inv1 = 1.f / (3.f * L1);
            if (vt == 8) {
#pragma unroll
                for (int nt = 0; nt < 8; nt++) {
                    int col = nt * 8 + t * 2;
                    if (qi0 < Tv) {
                        c0p[col] = o[nt][0] * inv0;
                        c0p[col + 1] = o[nt][1] * inv0;
                    }
                    if (qi1 < Tv) {
                        c1p[col] = o[nt][2] * inv1;
                        c1p[col + 1] = o[nt][3] * inv1;
                    }
                }
            } else if (vt == 11) {
#pragma unroll
                for (int nt = 0; nt < 8; nt++) {
                    int col = nt * 8 + t * 2;
                    if (qi0 < Tv) {
                        c0p[col] += o[nt][0] * inv0;
                        c0p[col + 1] += o[nt][1] * inv0;
                    }
                    if (qi1 < Tv) {
                        c1p[col] += o[nt][2] * inv1;
                        c1p[col + 1] += o[nt][3] * inv1;
                    }
                }
            } else {
#pragma unroll
                for (int nt = 0; nt < 8; nt++) {
                    int col = nt * 8 + t * 2;
                    if (qi0 < Tv) {
                        float v0 = c0p[col] + o[nt][0] * inv0;
                        float v1 = c0p[col + 1] + o[nt][1] * inv0;
                        *(uint32_t*)(c0ph + col) = pack_f16x2(v0, v1);
                    }
                    if (qi1 < Tv) {
                        float v2 = c1p[col] + o[nt][2] * inv1;
                        float v3 = c1p[col + 1] + o[nt][3] * inv1;
                        *(uint32_t*)(c1ph + col) = pack_f16x2(v2, v3);
                    }
                }
            }
#pragma unroll
            for (int nt = 0; nt < 8; nt++)
#pragma unroll
                for (int r = 0; r < 4; r++) o[nt][r] = 0.f;
            l0 = 0.f;
            l1 = 0.f;
        }
    }
}

// ---------------- launch ------------------------------------------------------
extern "C" void kernel_launch(void* const* d_in, const int* in_sizes, int n_in,
                              void* d_out, int out_size) {
    const float* x    = (const float*)d_in[0];
    const float* wq   = (const float*)d_in[1];
    const float* wdkv = (const float*)d_in[2];
    const float* wuk1 = (const float*)d_in[3];
    const float* wuk2 = (const float*)d_in[4];
    const float* wuk4 = (const float*)d_in[5];
    const float* wuv1 = (const float*)d_in[6];
    const float* wuv2 = (const float*)d_in[7];
    const float* wuv4 = (const float*)d_in[8];
    const float* wout = (const float*)d_in[9];
    const float* bout = (const float*)d_in[10];
    const float* tbl1 = (const float*)d_in[11];
    const float* tbl2 = (const float*)d_in[12];
    const float* tbl4 = (const float*)d_in[13];

    float* ctx;
    __half *qh, *lath, *lp2h, *lp4h, *kh, *vh, *k2h, *v2h, *k4h, *v4h, *wch, *xh, *ctxh;
    cudaGetSymbolAddress((void**)&qh, g_qh);
    cudaGetSymbolAddress((void**)&lath, g_lath);
    cudaGetSymbolAddress((void**)&lp2h, g_lp2h);
    cudaGetSymbolAddress((void**)&lp4h, g_lp4h);
    cudaGetSymbolAddress((void**)&kh, g_kh);
    cudaGetSymbolAddress((void**)&vh, g_vh);
    cudaGetSymbolAddress((void**)&k2h, g_k2h);
    cudaGetSymbolAddress((void**)&v2h, g_v2h);
    cudaGetSymbolAddress((void**)&k4h, g_k4h);
    cudaGetSymbolAddress((void**)&v4h, g_v4h);
    cudaGetSymbolAddress((void**)&ctx, g_ctx);
    cudaGetSymbolAddress((void**)&ctxh, g_ctxh);
    cudaGetSymbolAddress((void**)&wch, g_wch);
    cudaGetSymbolAddress((void**)&xh, g_xh);

    const int O_WQ = 0, O_WDKV = 589824, O_WUK1 = 786432, O_WUV1 = 983040;
    const int O_WUK2 = 1179648, O_WUV2 = 1376256, O_WUK4 = 1572864, O_WUV4 = 1769472;
    const int O_WOUT = 1966080;

    CvtArgs ca;
    ca.src[0] = wq;   ca.dst[0] = wch + O_WQ;   ca.n4[0] = 589824 / 4;
    ca.src[1] = wdkv; ca.dst[1] = wch + O_WDKV; ca.n4[1] = 196608 / 4;
    ca.src[2] = wuk1; ca.dst[2] = wch + O_WUK1; ca.n4[2] = 196608 / 4;
    ca.src[3] = wuv1; ca.dst[3] = wch + O_WUV1; ca.n4[3] = 196608 / 4;
    ca.src[4] = wuk2; ca.dst[4] = wch + O_WUK2; ca.n4[4] = 196608 / 4;
    ca.src[5] = wuv2; ca.dst[5] = wch + O_WUV2; ca.n4[5] = 196608 / 4;
    ca.src[6] = wuk4; ca.dst[6] = wch + O_WUK4; ca.n4[6] = 196608 / 4;
    ca.src[7] = wuv4; ca.dst[7] = wch + O_WUV4; ca.n4[7] = 196608 / 4;
    ca.src[8] = wout; ca.dst[8] = wch + O_WOUT; ca.n4[8] = 589824 / 4;
    ca.src[9] = x;    ca.dst[9] = xh;           ca.n4[9] = Bv * Tv * DMv / 4;

    const int GEMM_SMEM = 26880 * 4;           // 107,520 B
    const int ATT_SMEM = ATT_SMEM_WORDS * 4;   // 56,320 B
    cudaFuncSetAttribute(gemm_fp16, cudaFuncAttributeMaxDynamicSharedMemorySize,
                         GEMM_SMEM);
    cudaFuncSetAttribute(attn_fused, cudaFuncAttributeMaxDynamicSharedMemorySize,
                         ATT_SMEM);

    const int MQ = Bv * Tv;  // 9216

    cvtw_kernel<<<512, 256>>>(ca);

    // ---- QL: q-proj (x<6) + lat-proj (x>=6) in one launch, K=768 ----
    GemmJobs jql = {};
    jql.A[0] = xh;  jql.B[0] = wch + O_WQ;   jql.C[0] = qh;
    jql.M[0] = MQ;  jql.N[0] = DMv;          jql.fp16out[0] = 1;
    jql.A[1] = xh;  jql.B[1] = wch + O_WDKV; jql.C[1] = lath;
    jql.M[1] = MQ;  jql.N[1] = LDv;          jql.fp16out[1] = 1;
    gemm_fp16<<<dim3(8, 72, 1), 256, GEMM_SMEM>>>(jql, nullptr, DMv, 6);

    pool_kernel<<<(Bv * 144 * LDv + 255) / 256, 256>>>(lath, lp2h, 2, 12, Bv * 144 * LDv);
    pool_kernel<<<(Bv * 36 * LDv + 255) / 256, 256>>>(lath, lp4h, 4, 6, Bv * 36 * LDv);

    // ---- KV: all six k/v up-projections in one launch, K=256 ----
    GemmJobs jkv = {};
    jkv.A[0] = lath; jkv.B[0] = wch + O_WUK1; jkv.C[0] = kh;  jkv.M[0] = MQ;
    jkv.A[1] = lath; jkv.B[1] = wch + O_WUV1; jkv.C[1] = vh;  jkv.M[1] = MQ;
    jkv.A[2] = lp2h; jkv.B[2] = wch + O_WUK2; jkv.C[2] = k2h; jkv.M[2] = Bv * 144;
    jkv.A[3] = lp2h; jkv.B[3] = wch + O_WUV2; jkv.C[3] = v2h; jkv.M[3] = Bv * 144;
    jkv.A[4] = lp4h; jkv.B[4] = wch + O_WUK4; jkv.C[4] = k4h; jkv.M[4] = Bv * 36;
    jkv.A[5] = lp4h; jkv.B[5] = wch + O_WUV4; jkv.C[5] = v4h; jkv.M[5] = Bv * 36;
    for (int j = 0; j < 6; j++) { jkv.N[j] = DMv; jkv.fp16out[j] = 1; }
    gemm_fp16<<<dim3(6, 72, 6), 256, GEMM_SMEM>>>(jkv, nullptr, LDv, 6);

    attn_fused<<<dim3(5, NHv, Bv), 256, ATT_SMEM>>>(qh, kh, vh, k2h, v2h, k4h, v4h,
                                                    tbl1, tbl2, tbl4, ctx, ctxh);

    // ---- OUT: out-projection, fp32 + bias ----
    GemmJobs jo = {};
    jo.A[0] = ctxh; jo.B[0] = wch + O_WOUT; jo.C[0] = d_out;
    jo.M[0] = MQ;   jo.N[0] = DMv;          jo.fp16out[0] = 0;
    jo.A[1] = ctxh; jo.B[1] = wch + O_WOUT; jo.C[1] = d_out;
    jo.M[1] = MQ;   jo.N[1] = DMv;          jo.fp16out[1] = 0;
    gemm_fp16<<<dim3(6, 72, 1), 256, GEMM_SMEM>>>(jo, bout, DMv, 6);
}

// round 14
// speedup vs baseline: 1.1740x; 1.0311x over previous
#include <cuda_runtime.h>
#include <cuda_fp16.h>
#include <cstdint>
#include <cstddef>

#define Bv 16
#define Tv 576
#define NHv 12
#define HDv 64
#define DMv 768
#define LDv 256

// ---------------- scratch (static device allocations; no cudaMalloc) ---------
__device__ __half g_qh[Bv * Tv * DMv];
__device__ __half g_lath[Bv * Tv * LDv];
__device__ __half g_lp2h[Bv * 144 * LDv];
__device__ __half g_lp4h[Bv * 36 * LDv];
__device__ __half g_kh[Bv * Tv * DMv];
__device__ __half g_vh[Bv * Tv * DMv];
__device__ __half g_k2h[Bv * 144 * DMv];
__device__ __half g_v2h[Bv * 144 * DMv];
__device__ __half g_k4h[Bv * 36 * DMv];
__device__ __half g_v4h[Bv * 36 * DMv];
__device__ float g_ctx[Bv * Tv * DMv];
__device__ __half g_ctxh[Bv * Tv * DMv];
__device__ __half g_wch[2555904];        // fp16 weights
__device__ __half g_xh[Bv * Tv * DMv];   // fp16 x
__device__ float g_t2e[45684];           // bias tables * log2(e)

#define T2E_1 0
#define T2E_2 26508
#define T2E_4 39480
#define LOG2E 1.4426950408889634f

// ---------------- helpers -----------------------------------------------------
__device__ __forceinline__ uint32_t pack_f16x2(float lo, float hi) {
    uint32_t u;
    asm("cvt.rn.f16x2.f32 %0, %1, %2;" : "=r"(u) : "f"(hi), "f"(lo));
    return u;
}
__device__ __forceinline__ uint32_t ex2_f16x2(uint32_t x) {
    uint32_t r;
    asm("ex2.approx.f16x2 %0, %1;" : "=r"(r) : "r"(x));
    return r;
}

__device__ __forceinline__ void mma_f16(float& c0, float& c1, float& c2, float& c3,
                                        uint32_t a0, uint32_t a1, uint32_t a2, uint32_t a3,
                                        uint32_t b0, uint32_t b1) {
    asm volatile(
        "mma.sync.aligned.m16n8k16.row.col.f32.f16.f16.f32 "
        "{%0,%1,%2,%3}, {%4,%5,%6,%7}, {%8,%9}, {%0,%1,%2,%3};"
        : "+f"(c0), "+f"(c1), "+f"(c2), "+f"(c3)
        : "r"(a0), "r"(a1), "r"(a2), "r"(a3), "r"(b0), "r"(b1));
}

__device__ __forceinline__ void ldsm4(uint32_t& r0, uint32_t& r1, uint32_t& r2,
                                      uint32_t& r3, uint32_t addr) {
    asm volatile("ldmatrix.sync.aligned.m8n8.x4.shared.b16 {%0,%1,%2,%3}, [%4];"
                 : "=r"(r0), "=r"(r1), "=r"(r2), "=r"(r3) : "r"(addr));
}
__device__ __forceinline__ void ldsm4t(uint32_t& r0, uint32_t& r1, uint32_t& r2,
                                       uint32_t& r3, uint32_t addr) {
    asm volatile("ldmatrix.sync.aligned.m8n8.x4.trans.shared.b16 {%0,%1,%2,%3}, [%4];"
                 : "=r"(r0), "=r"(r1), "=r"(r2), "=r"(r3) : "r"(addr));
}

__device__ __forceinline__ void cpa16(uint32_t dst, const void* src) {
    asm volatile("cp.async.cg.shared.global [%0], [%1], 16;" :: "r"(dst), "l"(src));
}
__device__ __forceinline__ void cpa16z(uint32_t dst, const void* src, int pred) {
    asm volatile(
        "{\n\t.reg .pred p;\n\tsetp.ne.b32 p, %2, 0;\n\t"
        "@p cp.async.cg.shared.global [%0], [%1], 16;\n\t"
        "@!p cp.async.cg.shared.global [%0], [%1], 16, 0;\n\t}"
        :: "r"(dst), "l"(src), "r"(pred));
}
__device__ __forceinline__ void cp_commit() { asm volatile("cp.async.commit_group;"); }
__device__ __forceinline__ void cp_wait0() { asm volatile("cp.async.wait_group 0;"); }
__device__ __forceinline__ void cp_wait1() { asm volatile("cp.async.wait_group 1;"); }

// ---------------- fp16 pre-conversion, vectorized ------------------------------
struct CvtArgs {
    const float* src[10];
    __half* dst[10];
    int n4[10];
};
__global__ void cvtw_kernel(CvtArgs a) {
    int gid = blockIdx.x * blockDim.x + threadIdx.x;
    int stride = gridDim.x * blockDim.x;
#pragma unroll
    for (int s = 0; s < 10; s++) {
        const float4* sp = (const float4*)a.src[s];
        uint2* dp = (uint2*)a.dst[s];
        int n = a.n4[s];
        for (int i = gid; i < n; i += stride) {
            float4 v = sp[i];
            uint2 o;
            o.x = pack_f16x2(v.x, v.y);
            o.y = pack_f16x2(v.z, v.w);
            dp[i] = o;
        }
    }
}

// ---------------- bias tables * log2e -------------------------------------------
__global__ void cvttbl_kernel(const float* __restrict__ t1,
                              const float* __restrict__ t2,
                              const float* __restrict__ t4,
                              float* __restrict__ out) {
    int i = blockIdx.x * blockDim.x + threadIdx.x;
    if (i < 26508) out[T2E_1 + i] = t1[i] * LOG2E;
    if (i < 12972) out[T2E_2 + i] = t2[i] * LOG2E;
    if (i < 6204)  out[T2E_4 + i] = t4[i] * LOG2E;
}

// ---------------- fp16 tensor-core GEMM, multi-job, 3-stage, 128x128, BK=64 ----
struct GemmJobs {
    const __half* A[6];
    const __half* B[6];
    void* C[6];
    int M[6];
    int N[6];
    int fp16out[6];
};

__global__ __launch_bounds__(256, 2) void gemm_fp16(
    GemmJobs J, const float* __restrict__ bias, int K, int xsplit) {
    int job, bnIdx;
    if (gridDim.z > 1) {
        job = blockIdx.z;
        bnIdx = blockIdx.x;
    } else {
        job = (blockIdx.x >= xsplit) ? 1 : 0;
        bnIdx = job ? (blockIdx.x - xsplit) : blockIdx.x;
    }
    const __half* A = J.A[job];
    const __half* Bw = J.B[job];
    void* Cv = J.C[job];
    const int M = J.M[job];
    const int N = J.N[job];
    const int fp16out = J.fp16out[job];

    const int bm = blockIdx.y * 128;
    if (bm >= M) return;
    const int bn = bnIdx * 128;

    extern __shared__ uint32_t sm[];
    const int tid = threadIdx.x;
    const int lane = tid & 31;
    const int warp = tid >> 5;
    const int wm = (warp & 1) * 64;
    const int wn = (warp >> 1) * 32;
    const int g = lane >> 2;
    const int t = lane & 3;
    const int nk = K >> 6;
    uint32_t sb = (uint32_t)__cvta_generic_to_shared(sm);

    auto issue = [&](int it) {
        int buf = it % 3;
        int k0 = it << 6;
#pragma unroll
        for (int u = 0; u < 4; u++) {
            int idx = u * 256 + tid;
            int r = idx >> 3;
            int ch = idx & 7;
            int pred = (bm + r) < M;
            cpa16z(sb + (buf * 4608 + r * 36 + ch * 4) * 4,
                   A + (size_t)(bm + r) * K + k0 + ch * 8, pred);
        }
#pragma unroll
        for (int u = 0; u < 4; u++) {
            int idx = u * 256 + tid;
            int kk = idx >> 4;
            int ch = idx & 15;
            cpa16(sb + (13824 + buf * 4352 + kk * 68 + ch * 4) * 4,
                  Bw + (size_t)(k0 + kk) * N + bn + ch * 8);
        }
        cp_commit();
    };

    float c[4][4][4];
#pragma unroll
    for (int mt = 0; mt < 4; mt++)
#pragma unroll
        for (int nt = 0; nt < 4; nt++)
#pragma unroll
            for (int r = 0; r < 4; r++) c[mt][nt][r] = 0.f;

    issue(0);
    issue(1);

    const uint32_t aB = sb + (((wm + (lane & 15)) * 36) + (lane >> 4) * 4) * 4;
    const uint32_t bB = sb + 13824 * 4 +
        (((((lane >> 3) & 1) * 8 + (lane & 7)) * 68) + (wn >> 1) + (lane >> 4) * 4) * 4;

    for (int it = 0; it < nk; it++) {
        if (it + 1 < nk) cp_wait1(); else cp_wait0();
        __syncthreads();
        if (it + 2 < nk) issue(it + 2);
        const uint32_t aOff = (uint32_t)((it % 3) * 4608 * 4);
        const uint32_t bOff = (uint32_t)((it % 3) * 4352 * 4);
#pragma unroll
        for (int ks = 0; ks < 4; ks++) {
            uint32_t af[4][4];
#pragma unroll
            for (int mt = 0; mt < 4; mt++)
                ldsm4(af[mt][0], af[mt][1], af[mt][2], af[mt][3],
                      aB + aOff + (uint32_t)((mt * 16 * 36 + ks * 8) * 4));
            uint32_t bf[4][2];
#pragma unroll
            for (int nh = 0; nh < 2; nh++) {
                uint32_t v0, v1, v2, v3;
                ldsm4t(v0, v1, v2, v3,
                       bB + bOff + (uint32_t)((ks * 16 * 68 + nh * 8) * 4));
                bf[nh * 2][0] = v0; bf[nh * 2][1] = v1;
                bf[nh * 2 + 1][0] = v2; bf[nh * 2 + 1][1] = v3;
            }
#pragma unroll
            for (int mt = 0; mt < 4; mt++)
#pragma unroll
                for (int nt = 0; nt < 4; nt++)
                    mma_f16(c[mt][nt][0], c[mt][nt][1], c[mt][nt][2], c[mt][nt][3],
                            af[mt][0], af[mt][1], af[mt][2], af[mt][3],
                            bf[nt][0], bf[nt][1]);
        }
        __syncthreads();
    }

#pragma unroll
    for (int mt = 0; mt < 4; mt++) {
#pragma unroll
        for (int nt = 0; nt < 4; nt++) {
            int row0 = bm + wm + mt * 16 + g;
            int col = bn + wn + nt * 8 + t * 2;
            if (fp16out) {
                __half* Ch = (__half*)Cv;
                uint32_t h01 = pack_f16x2(c[mt][nt][0], c[mt][nt][1]);
                uint32_t h23 = pack_f16x2(c[mt][nt][2], c[mt][nt][3]);
                if (row0 < M) *(uint32_t*)(Ch + (size_t)row0 * N + col) = h01;
                if (row0 + 8 < M) *(uint32_t*)(Ch + (size_t)(row0 + 8) * N + col) = h23;
            } else {
                float* C = (float*)Cv;
                float b0 = bias ? bias[col] : 0.f;
                float b1 = bias ? bias[col + 1] : 0.f;
                if (row0 < M)
                    *(float2*)(C + (size_t)row0 * N + col) =
                        make_float2(c[mt][nt][0] + b0, c[mt][nt][1] + b1);
                if (row0 + 8 < M)
                    *(float2*)(C + (size_t)(row0 + 8) * N + col) =
                        make_float2(c[mt][nt][2] + b0, c[mt][nt][3] + b1);
            }
        }
    }
}

// ---------------- fused s=2 + s=4 mean pooling ----------------------------------
__global__ void pool_both(const __half* __restrict__ lat,
                          __half* __restrict__ lp2, __half* __restrict__ lp4) {
    const int N2 = Bv * 144 * LDv;
    const int N4 = Bv * 36 * LDv;
    int idx = blockIdx.x * blockDim.x + threadIdx.x;
    if (idx < N2) {
        int c = idx & (LDv - 1);
        int rest = idx >> 8;
        int cell = rest % 144;
        int b = rest / 144;
        int gh = cell / 12, gw = cell % 12;
        float sum = 0.f;
        for (int i = 0; i < 2; i++)
            for (int j = 0; j < 2; j++)
                sum += __half2float(
                    lat[((size_t)(b * Tv) + (gh * 2 + i) * 24 + (gw * 2 + j)) * LDv + c]);
        lp2[idx] = __float2half(sum * 0.25f);
    } else if (idx < N2 + N4) {
        int k = idx - N2;
        int c = k & (LDv - 1);
        int rest = k >> 8;
        int cell = rest % 36;
        int b = rest / 36;
        int gh = cell / 6, gw = cell % 6;
        float sum = 0.f;
        for (int i = 0; i < 4; i++)
            for (int j = 0; j < 4; j++)
                sum += __half2float(
                    lat[((size_t)(b * Tv) + (gh * 4 + i) * 24 + (gw * 4 + j)) * LDv + c]);
        lp4[k] = __float2half(sum * 0.0625f);
    }
}

// ---------------- fused 3-scale fp16 flash attention ---------------------------
// s=1 fast path (separable integer bias); exp via ex2.approx.f16x2 on
// log2e-prescaled tables; final segment writes ctxh directly.
#define ATT_SMEM_WORDS 14080

__global__ __launch_bounds__(256, 2) void attn_fused(
    const __half* __restrict__ qbuf,
    const __half* __restrict__ k1, const __half* __restrict__ v1,
    const __half* __restrict__ k2, const __half* __restrict__ v2,
    const __half* __restrict__ k4, const __half* __restrict__ v4,
    const float* __restrict__ t2e, float* __restrict__ ctx,
    __half* __restrict__ ctxh) {
    extern __shared__ uint32_t smu[];
    float* khcs = (float*)(smu + 13824);
    float* kwcs = khcs + 128;
    int* ibase = (int*)khcs;
    uint32_t sb = (uint32_t)__cvta_generic_to_shared(smu);

    const int b = blockIdx.z;
    const int h = blockIdx.y;
    const int q0 = blockIdx.x * 128;
    const int tid = threadIdx.x;
    const int lane = tid & 31;
    const int w = tid >> 5;
    const int g = lane >> 2;
    const int t = lane & 3;
    const int lr0 = w * 16 + g;
    const int lr1 = lr0 + 8;

    auto issue_kv = [&](int vt) {
        const __half *kb, *vb;
        int Kt, kt;
        if (vt < 9) {
            kb = k1 + (size_t)b * 576 * DMv + h * HDv;
            vb = v1 + (size_t)b * 576 * DMv + h * HDv;
            Kt = 576; kt = vt;
        } else if (vt < 12) {
            kb = k2 + (size_t)b * 144 * DMv + h * HDv;
            vb = v2 + (size_t)b * 144 * DMv + h * HDv;
            Kt = 144; kt = vt - 9;
        } else {
            kb = k4 + (size_t)b * 36 * DMv + h * HDv;
            vb = v4 + (size_t)b * 36 * DMv + h * HDv;
            Kt = 36; kt = 0;
        }
        int buf = vt & 1;
#pragma unroll
        for (int u = 0; u < 2; u++) {
            int idx = u * 256 + tid;
            int r = idx >> 3;
            int c8 = (idx & 7) << 3;
            int kg = kt * 64 + r;
            int pred = kg < Kt;
            cpa16z(sb + (buf * 2304 + r * 36 + (c8 >> 1)) * 4,
                   kb + (size_t)kg * DMv + c8, pred);
            cpa16z(sb + (4608 + buf * 2304 + r * 36 + (c8 >> 1)) * 4,
                   vb + (size_t)kg * DMv + c8, pred);
        }
    };

    const __half* qsrc = qbuf + (size_t)(b * Tv) * DMv + h * HDv;
#pragma unroll
    for (int u = 0; u < 4; u++) {
        int idx = u * 256 + tid;
        int r = idx >> 3;
        int c8 = (idx & 7) << 3;
        int row = q0 + r;
        if (row > Tv - 1) row = Tv - 1;
        *(uint4*)&smu[9216 + r * 36 + (c8 >> 1)] =
            *(const uint4*)(qsrc + (size_t)row * DMv + c8);
    }
    issue_kv(0);
    cp_commit();
    __syncthreads();

    uint32_t qf[4][4];
#pragma unroll
    for (int ks = 0; ks < 4; ks++) {
        qf[ks][0] = smu[9216 + lr0 * 36 + ks * 8 + t];
        qf[ks][1] = smu[9216 + lr1 * 36 + ks * 8 + t];
        qf[ks][2] = smu[9216 + lr0 * 36 + ks * 8 + t + 4];
        qf[ks][3] = smu[9216 + lr1 * 36 + ks * 8 + t + 4];
    }

    float o[8][4];
#pragma unroll
    for (int nt = 0; nt < 8; nt++)
#pragma unroll
        for (int r = 0; r < 4; r++) o[nt][r] = 0.f;
    float l0 = 0.f, l1 = 0.f;

    const float scl = 0.125f * LOG2E;   // folded log2e
    const int qi0 = q0 + lr0;
    const int qi1 = q0 + lr1;
    const int qc0 = qi0 < Tv ? qi0 : Tv - 1;
    const int qc1 = qi1 < Tv ? qi1 : Tv - 1;
    const int qh0i = qc0 / 24, qw0i = qc0 % 24;
    const int qh1i = qc1 / 24, qw1i = qc1 % 24;
    const int qoff0 = qh0i * 47 + qw0i;
    const int qoff1 = qh1i * 47 + qw1i;
    const float qh0 = (float)qh0i, qw0 = (float)qw0i;
    const float qh1 = (float)qh1i, qw1 = (float)qw1i;
    float* c0p = ctx + ((size_t)(b * Tv + qc0)) * DMv + h * HDv;
    float* c1p = ctx + ((size_t)(b * Tv + qc1)) * DMv + h * HDv;
    __half* c0ph = ctxh + ((size_t)(b * Tv + qc0)) * DMv + h * HDv;
    __half* c1ph = ctxh + ((size_t)(b * Tv + qc1)) * DMv + h * HDv;

    const uint32_t krow = sb + (((lane & 7) * 36) + ((lane >> 3) << 2)) * 4;
    const uint32_t vrow = sb + 4608 * 4 +
        (((((lane >> 3) & 1) * 8 + (lane & 7)) * 36) + ((lane >> 4) << 2)) * 4;

    for (int vt = 0; vt < 13; vt++) {
        int Kt, kt, gw_, s_, tw_;
        const float* tb;
        if (vt < 9)       { Kt = 576; kt = vt;      gw_ = 24; s_ = 1; tw_ = 47; tb = t2e + T2E_1 + h * (47 * 47); }
        else if (vt < 12) { Kt = 144; kt = vt - 9;  gw_ = 12; s_ = 2; tw_ = 23; tb = t2e + T2E_2 + h * (47 * 23); }
        else              { Kt = 36;  kt = 0;       gw_ = 6;  s_ = 4; tw_ = 11; tb = t2e + T2E_4 + h * (47 * 11); }
        const float hctr = 0.5f * (float)(s_ - 1);
        const int buf = vt & 1;

        cp_wait0();
        if (tid < 64) {
            int kg = kt * 64 + tid;
            if (vt < 9) {
                ibase[buf * 64 + tid] = (23 - kg / 24) * 47 + (23 - kg % 24);
            } else if (kg < Kt) {
                khcs[buf * 64 + tid] = (float)((kg / gw_) * s_) + hctr;
                kwcs[buf * 64 + tid] = (float)((kg % gw_) * s_) + hctr;
            }
        }
        __syncthreads();
        if (vt + 1 < 13) { issue_kv(vt + 1); cp_commit(); }

        const uint32_t kbase = krow + (buf * 2304) * 4;
        const uint32_t vbase = vrow + (buf * 2304) * 4;

        uint32_t pA[8], pB[8];
        if (vt < 9) {
            const int* ib = ibase + buf * 64;
#pragma unroll
            for (int nt = 0; nt < 8; nt++) {
                uint32_t r0, r1, r2, r3, r4, r5, r6, r7;
                ldsm4(r0, r1, r2, r3, kbase + (nt * 8 * 36) * 4);
                ldsm4(r4, r5, r6, r7, kbase + (nt * 8 * 36) * 4 + 64);
                float s0 = 0.f, s1 = 0.f, s2 = 0.f, s3 = 0.f;
                mma_f16(s0, s1, s2, s3, qf[0][0], qf[0][1], qf[0][2], qf[0][3], r0, r1);
                mma_f16(s0, s1, s2, s3, qf[1][0], qf[1][1], qf[1][2], qf[1][3], r2, r3);
                mma_f16(s0, s1, s2, s3, qf[2][0], qf[2][1], qf[2][2], qf[2][3], r4, r5);
                mma_f16(s0, s1, s2, s3, qf[3][0], qf[3][1], qf[3][2], qf[3][3], r6, r7);

                int lc = nt * 8 + t * 2;
                int bA = ib[lc], bB2 = ib[lc + 1];
                float x0 = s0 * scl + __ldg(tb + bA + qoff0);
                float x1 = s1 * scl + __ldg(tb + bB2 + qoff0);
                float x2 = s2 * scl + __ldg(tb + bA + qoff1);
                float x3 = s3 * scl + __ldg(tb + bB2 + qoff1);
                uint32_t eA = ex2_f16x2(pack_f16x2(x0, x1));
                uint32_t eB = ex2_f16x2(pack_f16x2(x2, x3));
                float2 fA = __half22float2(*(__half2*)&eA);
                float2 fB = __half22float2(*(__half2*)&eB);
                l0 += fA.x + fA.y;
                l1 += fB.x + fB.y;
                pA[nt] = eA;
                pB[nt] = eB;
            }
        } else {
#pragma unroll
            for (int nt = 0; nt < 8; nt++) {
                uint32_t r0, r1, r2, r3, r4, r5, r6, r7;
                ldsm4(r0, r1, r2, r3, kbase + (nt * 8 * 36) * 4);
                ldsm4(r4, r5, r6, r7, kbase + (nt * 8 * 36) * 4 + 64);
                float s0 = 0.f, s1 = 0.f, s2 = 0.f, s3 = 0.f;
                mma_f16(s0, s1, s2, s3, qf[0][0], qf[0][1], qf[0][2], qf[0][3], r0, r1);
                mma_f16(s0, s1, s2, s3, qf[1][0], qf[1][1], qf[1][2], qf[1][3], r2, r3);
                mma_f16(s0, s1, s2, s3, qf[2][0], qf[2][1], qf[2][2], qf[2][3], r4, r5);
                mma_f16(s0, s1, s2, s3, qf[3][0], qf[3][1], qf[3][2], qf[3][3], r6, r7);

                int lc = nt * 8 + t * 2;
                int kg = kt * 64 + lc;
                if (kg < Kt) {
                    float khcA = khcs[buf * 64 + lc], kwcA = kwcs[buf * 64 + lc];
                    float khcB = khcs[buf * 64 + lc + 1], kwcB = kwcs[buf * 64 + lc + 1];
                    int rh0a = (int)(qh0 - khcA) + 23, rw0a = (int)(qw0 - kwcA) + (gw_ - 1);
                    int rh0b = (int)(qh0 - khcB) + 23, rw0b = (int)(qw0 - kwcB) + (gw_ - 1);
                    int rh1a = (int)(qh1 - khcA) + 23, rw1a = (int)(qw1 - kwcA) + (gw_ - 1);
                    int rh1b = (int)(qh1 - khcB) + 23, rw1b = (int)(qw1 - kwcB) + (gw_ - 1);
                    float x0 = s0 * scl + __ldg(&tb[rh0a * tw_ + rw0a]);
                    float x1 = s1 * scl + __ldg(&tb[rh0b * tw_ + rw0b]);
                    float x2 = s2 * scl + __ldg(&tb[rh1a * tw_ + rw1a]);
                    float x3 = s3 * scl + __ldg(&tb[rh1b * tw_ + rw1b]);
                    uint32_t eA = ex2_f16x2(pack_f16x2(x0, x1));
                    uint32_t eB = ex2_f16x2(pack_f16x2(x2, x3));
                    float2 fA = __half22float2(*(__half2*)&eA);
                    float2 fB = __half22float2(*(__half2*)&eB);
                    l0 += fA.x + fA.y;
                    l1 += fB.x + fB.y;
                    pA[nt] = eA;
                    pB[nt] = eB;
                } else {
                    pA[nt] = 0u;
                    pB[nt] = 0u;
                }
            }
        }

#pragma unroll
        for (int ks = 0; ks < 4; ks++) {
            uint32_t a0 = pA[2 * ks], a1 = pB[2 * ks];
            uint32_t a2 = pA[2 * ks + 1], a3 = pB[2 * ks + 1];
#pragma unroll
            for (int p = 0; p < 4; p++) {
                uint32_t v0, v1, v2, v3;
                ldsm4t(v0, v1, v2, v3, vbase + (ks * 16 * 36 + p * 8) * 4);
                mma_f16(o[2 * p][0], o[2 * p][1], o[2 * p][2], o[2 * p][3],
                        a0, a1, a2, a3, v0, v1);
                mma_f16(o[2 * p + 1][0], o[2 * p + 1][1], o[2 * p + 1][2], o[2 * p + 1][3],
                        a0, a1, a2, a3, v2, v3);
            }
        }

        if (vt == 8 || vt == 11 || vt == 12) {
            float L0 = l0, L1 = l1;
            L0 += __shfl_xor_sync(0xffffffffu, L0, 1);
            L0 += __shfl_xor_sync(0xffffffffu, L0, 2);
            L1 += __shfl_xor_sync(0xffffffffu, L1, 1);
            L1 += __shfl_xor_sync(0xffffffffu, L1, 2);
            float inv0 = 1.f / (3.f * L0);
            float inv1 = 1.f / (3.f * L1);
            if (vt == 8) {
#pragma unroll
                for (int nt = 0; nt < 8; nt++) {
                    int col = nt * 8 + t * 2;
                    if (qi0 < Tv) {
                        c0p[col] = o[nt][0] * inv0;
                        c0p[col + 1] = o[nt][1] * inv0;
                    }
                    if (qi1 < Tv) {
                        c1p[col] = o[nt][2] * inv1;
                        c1p[col + 1] = o[nt][3] * inv1;
                    }
                }
            } else if (vt == 11) {
#pragma unroll
                for (int nt = 0; nt < 8; nt++) {
                    int col = nt * 8 + t * 2;
                    if (qi0 < Tv) {
                        c0p[col] += o[nt][0] * inv0;
                        c0p[col + 1] += o[nt][1] * inv0;
                    }
                    if (qi1 < Tv) {
                        c1p[col] += o[nt][2] * inv1;
                        c1p[col + 1] += o[nt][3] * inv1;
                    }
                }
            } else {
#pragma unroll
                for (int nt = 0; nt < 8; nt++) {
                    int col = nt * 8 + t * 2;
                    if (qi0 < Tv) {
                        float v0 = c0p[col] + o[nt][0] * inv0;
                        float v1 = c0p[col + 1] + o[nt][1] * inv0;
                        *(uint32_t*)(c0ph + col) = pack_f16x2(v0, v1);
                    }
                    if (qi1 < Tv) {
                        float v2 = c1p[col] + o[nt][2] * inv1;
                        float v3 = c1p[col + 1] + o[nt][3] * inv1;
                        *(uint32_t*)(c1ph + col) = pack_f16x2(v2, v3);
                    }
                }
            }
#pragma unroll
            for (int nt = 0; nt < 8; nt++)
#pragma unroll
                for (int r = 0; r < 4; r++) o[nt][r] = 0.f;
            l0 = 0.f;
            l1 = 0.f;
        }
    }
}

// ---------------- launch ------------------------------------------------------
extern "C" void kernel_launch(void* const* d_in, const int* in_sizes, int n_in,
                              void* d_out, int out_size) {
    const float* x    = (const float*)d_in[0];
    const float* wq   = (const float*)d_in[1];
    const float* wdkv = (const float*)d_in[2];
    const float* wuk1 = (const float*)d_in[3];
    const float* wuk2 = (const float*)d_in[4];
    const float* wuk4 = (const float*)d_in[5];
    const float* wuv1 = (const float*)d_in[6];
    const float* wuv2 = (const float*)d_in[7];
    const float* wuv4 = (const float*)d_in[8];
    const float* wout = (const float*)d_in[9];
    const float* bout = (const float*)d_in[10];
    const float* tbl1 = (const float*)d_in[11];
    const float* tbl2 = (const float*)d_in[12];
    const float* tbl4 = (const float*)d_in[13];

    float *ctx, *t2e;
    __half *qh, *lath, *lp2h, *lp4h, *kh, *vh, *k2h, *v2h, *k4h, *v4h, *wch, *xh, *ctxh;
    cudaGetSymbolAddress((void**)&qh, g_qh);
    cudaGetSymbolAddress((void**)&lath, g_lath);
    cudaGetSymbolAddress((void**)&lp2h, g_lp2h);
    cudaGetSymbolAddress((void**)&lp4h, g_lp4h);
    cudaGetSymbolAddress((void**)&kh, g_kh);
    cudaGetSymbolAddress((void**)&vh, g_vh);
    cudaGetSymbolAddress((void**)&k2h, g_k2h);
    cudaGetSymbolAddress((void**)&v2h, g_v2h);
    cudaGetSymbolAddress((void**)&k4h, g_k4h);
    cudaGetSymbolAddress((void**)&v4h, g_v4h);
    cudaGetSymbolAddress((void**)&ctx, g_ctx);
    cudaGetSymbolAddress((void**)&ctxh, g_ctxh);
    cudaGetSymbolAddress((void**)&wch, g_wch);
    cudaGetSymbolAddress((void**)&xh, g_xh);
    cudaGetSymbolAddress((void**)&t2e, g_t2e);

    const int O_WQ = 0, O_WDKV = 589824, O_WUK1 = 786432, O_WUV1 = 983040;
    const int O_WUK2 = 1179648, O_WUV2 = 1376256, O_WUK4 = 1572864, O_WUV4 = 1769472;
    const int O_WOUT = 1966080;

    CvtArgs ca;
    ca.src[0] = wq;   ca.dst[0] = wch + O_WQ;   ca.n4[0] = 589824 / 4;
    ca.src[1] = wdkv; ca.dst[1] = wch + O_WDKV; ca.n4[1] = 196608 / 4;
    ca.src[2] = wuk1; ca.dst[2] = wch + O_WUK1; ca.n4[2] = 196608 / 4;
    ca.src[3] = wuv1; ca.dst[3] = wch + O_WUV1; ca.n4[3] = 196608 / 4;
    ca.src[4] = wuk2; ca.dst[4] = wch + O_WUK2; ca.n4[4] = 196608 / 4;
    ca.src[5] = wuv2; ca.dst[5] = wch + O_WUV2; ca.n4[5] = 196608 / 4;
    ca.src[6] = wuk4; ca.dst[6] = wch + O_WUK4; ca.n4[6] = 196608 / 4;
    ca.src[7] = wuv4; ca.dst[7] = wch + O_WUV4; ca.n4[7] = 196608 / 4;
    ca.src[8] = wout; ca.dst[8] = wch + O_WOUT; ca.n4[8] = 589824 / 4;
    ca.src[9] = x;    ca.dst[9] = xh;           ca.n4[9] = Bv * Tv * DMv / 4;

    const int GEMM_SMEM = 26880 * 4;           // 107,520 B
    const int ATT_SMEM = ATT_SMEM_WORDS * 4;   // 56,320 B
    cudaFuncSetAttribute(gemm_fp16, cudaFuncAttributeMaxDynamicSharedMemorySize,
                         GEMM_SMEM);
    cudaFuncSetAttribute(attn_fused, cudaFuncAttributeMaxDynamicSharedMemorySize,
                         ATT_SMEM);

    const int MQ = Bv * Tv;  // 9216

    cvttbl_kernel<<<(26508 + 255) / 256, 256>>>(tbl1, tbl2, tbl4, t2e);
    cvtw_kernel<<<512, 256>>>(ca);

    // ---- QL: q-proj (x<6) + lat-proj (x>=6), K=768 ----
    GemmJobs jql = {};
    jql.A[0] = xh;  jql.B[0] = wch + O_WQ;   jql.C[0] = qh;
    jql.M[0] = MQ;  jql.N[0] = DMv;          jql.fp16out[0] = 1;
    jql.A[1] = xh;  jql.B[1] = wch + O_WDKV; jql.C[1] = lath;
    jql.M[1] = MQ;  jql.N[1] = LDv;          jql.fp16out[1] = 1;
    gemm_fp16<<<dim3(8, 72, 1), 256, GEMM_SMEM>>>(jql, nullptr, DMv, 6);

    pool_both<<<(Bv * 180 * LDv + 255) / 256, 256>>>(lath, lp2h, lp4h);

    // ---- KV: all six k/v up-projections, K=256 ----
    GemmJobs jkv = {};
    jkv.A[0] = lath; jkv.B[0] = wch + O_WUK1; jkv.C[0] = kh;  jkv.M[0] = MQ;
    jkv.A[1] = lath; jkv.B[1] = wch + O_WUV1; jkv.C[1] = vh;  jkv.M[1] = MQ;
    jkv.A[2] = lp2h; jkv.B[2] = wch + O_WUK2; jkv.C[2] = k2h; jkv.M[2] = Bv * 144;
    jkv.A[3] = lp2h; jkv.B[3] = wch + O_WUV2; jkv.C[3] = v2h; jkv.M[3] = Bv * 144;
    jkv.A[4] = lp4h; jkv.B[4] = wch + O_WUK4; jkv.C[4] = k4h; jkv.M[4] = Bv * 36;
    jkv.A[5] = lp4h; jkv.B[5] = wch + O_WUV4; jkv.C[5] = v4h; jkv.M[5] = Bv * 36;
    for (int j = 0; j < 6; j++) { jkv.N[j] = DMv; jkv.fp16out[j] = 1; }
    gemm_fp16<<<dim3(6, 72, 6), 256, GEMM_SMEM>>>(jkv, nullptr, LDv, 6);

    attn_fused<<<dim3(5, NHv, Bv), 256, ATT_SMEM>>>(qh, kh, vh, k2h, v2h, k4h, v4h,
                                                    t2e, ctx, ctxh);

    // ---- OUT: out-projection, fp32 + bias ----
    GemmJobs jo = {};
    jo.A[0] = ctxh; jo.B[0] = wch + O_WOUT; jo.C[0] = d_out;
    jo.M[0] = MQ;   jo.N[0] = DMv;          jo.fp16out[0] = 0;
    jo.A[1] = ctxh; jo.B[1] = wch + O_WOUT; jo.C[1] = d_out;
    jo.M[1] = MQ;   jo.N[1] = DMv;          jo.fp16out[1] = 0;
    gemm_fp16<<<dim3(6, 72, 1), 256, GEMM_SMEM>>>(jo, bout, DMv, 6);
}

// round 15
// speedup vs baseline: 1.2425x; 1.0583x over previous
#include <cuda_runtime.h>
#include <cuda_fp16.h>
#include <cstdint>
#include <cstddef>

#define Bv 16
#define Tv 576
#define NHv 12
#define HDv 64
#define DMv 768
#define LDv 256

// ---------------- scratch (static device allocations; no cudaMalloc) ---------
__device__ __half g_qh[Bv * Tv * DMv];
__device__ __half g_lath[Bv * Tv * LDv];
__device__ __half g_lp2h[Bv * 144 * LDv];
__device__ __half g_lp4h[Bv * 36 * LDv];
__device__ __half g_kh[Bv * Tv * DMv];
__device__ __half g_vh[Bv * Tv * DMv];
__device__ __half g_k2h[Bv * 144 * DMv];
__device__ __half g_v2h[Bv * 144 * DMv];
__device__ __half g_k4h[Bv * 36 * DMv];
__device__ __half g_v4h[Bv * 36 * DMv];
__device__ __half g_ctxh[Bv * Tv * DMv];
__device__ __half g_wch[2555904];        // fp16 weights
__device__ __half g_xh[Bv * Tv * DMv];   // fp16 x
__device__ float g_t2e[45684];           // bias tables * log2(e)

#define T2E_1 0
#define T2E_2 26508
#define T2E_4 39480
#define LOG2E 1.4426950408889634f

// ---------------- helpers -----------------------------------------------------
__device__ __forceinline__ uint32_t pack_f16x2(float lo, float hi) {
    uint32_t u;
    asm("cvt.rn.f16x2.f32 %0, %1, %2;" : "=r"(u) : "f"(hi), "f"(lo));
    return u;
}
__device__ __forceinline__ uint32_t ex2_f16x2(uint32_t x) {
    uint32_t r;
    asm("ex2.approx.f16x2 %0, %1;" : "=r"(r) : "r"(x));
    return r;
}

__device__ __forceinline__ void mma_f16(float& c0, float& c1, float& c2, float& c3,
                                        uint32_t a0, uint32_t a1, uint32_t a2, uint32_t a3,
                                        uint32_t b0, uint32_t b1) {
    asm volatile(
        "mma.sync.aligned.m16n8k16.row.col.f32.f16.f16.f32 "
        "{%0,%1,%2,%3}, {%4,%5,%6,%7}, {%8,%9}, {%0,%1,%2,%3};"
        : "+f"(c0), "+f"(c1), "+f"(c2), "+f"(c3)
        : "r"(a0), "r"(a1), "r"(a2), "r"(a3), "r"(b0), "r"(b1));
}

__device__ __forceinline__ void ldsm4(uint32_t& r0, uint32_t& r1, uint32_t& r2,
                                      uint32_t& r3, uint32_t addr) {
    asm volatile("ldmatrix.sync.aligned.m8n8.x4.shared.b16 {%0,%1,%2,%3}, [%4];"
                 : "=r"(r0), "=r"(r1), "=r"(r2), "=r"(r3) : "r"(addr));
}
__device__ __forceinline__ void ldsm4t(uint32_t& r0, uint32_t& r1, uint32_t& r2,
                                       uint32_t& r3, uint32_t addr) {
    asm volatile("ldmatrix.sync.aligned.m8n8.x4.trans.shared.b16 {%0,%1,%2,%3}, [%4];"
                 : "=r"(r0), "=r"(r1), "=r"(r2), "=r"(r3) : "r"(addr));
}

__device__ __forceinline__ void cpa16(uint32_t dst, const void* src) {
    asm volatile("cp.async.cg.shared.global [%0], [%1], 16;" :: "r"(dst), "l"(src));
}
__device__ __forceinline__ void cpa16z(uint32_t dst, const void* src, int pred) {
    asm volatile(
        "{\n\t.reg .pred p;\n\tsetp.ne.b32 p, %2, 0;\n\t"
        "@p cp.async.cg.shared.global [%0], [%1], 16;\n\t"
        "@!p cp.async.cg.shared.global [%0], [%1], 16, 0;\n\t}"
        :: "r"(dst), "l"(src), "r"(pred));
}
__device__ __forceinline__ void cp_commit() { asm volatile("cp.async.commit_group;"); }
__device__ __forceinline__ void cp_wait0() { asm volatile("cp.async.wait_group 0;"); }
__device__ __forceinline__ void cp_wait1() { asm volatile("cp.async.wait_group 1;"); }

// ---------------- fp16 pre-conversion + bias-table scaling, one kernel ---------
struct CvtArgs {
    const float* src[10];
    __half* dst[10];
    int n4[10];
    const float* t1;
    const float* t2;
    const float* t4;
    float* t2e;
};
__global__ void cvtw_kernel(CvtArgs a) {
    int gid = blockIdx.x * blockDim.x + threadIdx.x;
    int stride = gridDim.x * blockDim.x;
#pragma unroll
    for (int s = 0; s < 10; s++) {
        const float4* sp = (const float4*)a.src[s];
        uint2* dp = (uint2*)a.dst[s];
        int n = a.n4[s];
        for (int i = gid; i < n; i += stride) {
            float4 v = sp[i];
            uint2 o;
            o.x = pack_f16x2(v.x, v.y);
            o.y = pack_f16x2(v.z, v.w);
            dp[i] = o;
        }
    }
    // bias tables * log2e
    for (int i = gid; i < 26508; i += stride) a.t2e[T2E_1 + i] = a.t1[i] * LOG2E;
    for (int i = gid; i < 12972; i += stride) a.t2e[T2E_2 + i] = a.t2[i] * LOG2E;
    for (int i = gid; i < 6204; i += stride)  a.t2e[T2E_4 + i] = a.t4[i] * LOG2E;
}

// ---------------- fp16 tensor-core GEMM, multi-job, 3-stage, 128x128, BK=64 ----
struct GemmJobs {
    const __half* A[6];
    const __half* B[6];
    void* C[6];
    int M[6];
    int N[6];
    int fp16out[6];
};

__global__ __launch_bounds__(256, 2) void gemm_fp16(
    GemmJobs J, const float* __restrict__ bias, int K, int xsplit) {
    int job, bnIdx;
    if (gridDim.z > 1) {
        job = blockIdx.z;
        bnIdx = blockIdx.x;
    } else {
        job = (blockIdx.x >= xsplit) ? 1 : 0;
        bnIdx = job ? (blockIdx.x - xsplit) : blockIdx.x;
    }
    const __half* A = J.A[job];
    const __half* Bw = J.B[job];
    void* Cv = J.C[job];
    const int M = J.M[job];
    const int N = J.N[job];
    const int fp16out = J.fp16out[job];

    const int bm = blockIdx.y * 128;
    if (bm >= M) return;
    const int bn = bnIdx * 128;

    extern __shared__ uint32_t sm[];
    const int tid = threadIdx.x;
    const int lane = tid & 31;
    const int warp = tid >> 5;
    const int wm = (warp & 1) * 64;
    const int wn = (warp >> 1) * 32;
    const int g = lane >> 2;
    const int t = lane & 3;
    const int nk = K >> 6;
    uint32_t sb = (uint32_t)__cvta_generic_to_shared(sm);

    auto issue = [&](int it) {
        int buf = it % 3;
        int k0 = it << 6;
#pragma unroll
        for (int u = 0; u < 4; u++) {
            int idx = u * 256 + tid;
            int r = idx >> 3;
            int ch = idx & 7;
            int pred = (bm + r) < M;
            cpa16z(sb + (buf * 4608 + r * 36 + ch * 4) * 4,
                   A + (size_t)(bm + r) * K + k0 + ch * 8, pred);
        }
#pragma unroll
        for (int u = 0; u < 4; u++) {
            int idx = u * 256 + tid;
            int kk = idx >> 4;
            int ch = idx & 15;
            cpa16(sb + (13824 + buf * 4352 + kk * 68 + ch * 4) * 4,
                  Bw + (size_t)(k0 + kk) * N + bn + ch * 8);
        }
        cp_commit();
    };

    float c[4][4][4];
#pragma unroll
    for (int mt = 0; mt < 4; mt++)
#pragma unroll
        for (int nt = 0; nt < 4; nt++)
#pragma unroll
            for (int r = 0; r < 4; r++) c[mt][nt][r] = 0.f;

    issue(0);
    issue(1);

    const uint32_t aB = sb + (((wm + (lane & 15)) * 36) + (lane >> 4) * 4) * 4;
    const uint32_t bB = sb + 13824 * 4 +
        (((((lane >> 3) & 1) * 8 + (lane & 7)) * 68) + (wn >> 1) + (lane >> 4) * 4) * 4;

    for (int it = 0; it < nk; it++) {
        if (it + 1 < nk) cp_wait1(); else cp_wait0();
        __syncthreads();
        if (it + 2 < nk) issue(it + 2);
        const uint32_t aOff = (uint32_t)((it % 3) * 4608 * 4);
        const uint32_t bOff = (uint32_t)((it % 3) * 4352 * 4);
#pragma unroll
        for (int ks = 0; ks < 4; ks++) {
            uint32_t af[4][4];
#pragma unroll
            for (int mt = 0; mt < 4; mt++)
                ldsm4(af[mt][0], af[mt][1], af[mt][2], af[mt][3],
                      aB + aOff + (uint32_t)((mt * 16 * 36 + ks * 8) * 4));
            uint32_t bf[4][2];
#pragma unroll
            for (int nh = 0; nh < 2; nh++) {
                uint32_t v0, v1, v2, v3;
                ldsm4t(v0, v1, v2, v3,
                       bB + bOff + (uint32_t)((ks * 16 * 68 + nh * 8) * 4));
                bf[nh * 2][0] = v0; bf[nh * 2][1] = v1;
                bf[nh * 2 + 1][0] = v2; bf[nh * 2 + 1][1] = v3;
            }
#pragma unroll
            for (int mt = 0; mt < 4; mt++)
#pragma unroll
                for (int nt = 0; nt < 4; nt++)
                    mma_f16(c[mt][nt][0], c[mt][nt][1], c[mt][nt][2], c[mt][nt][3],
                            af[mt][0], af[mt][1], af[mt][2], af[mt][3],
                            bf[nt][0], bf[nt][1]);
        }
        __syncthreads();
    }

#pragma unroll
    for (int mt = 0; mt < 4; mt++) {
#pragma unroll
        for (int nt = 0; nt < 4; nt++) {
            int row0 = bm + wm + mt * 16 + g;
            int col = bn + wn + nt * 8 + t * 2;
            if (fp16out) {
                __half* Ch = (__half*)Cv;
                uint32_t h01 = pack_f16x2(c[mt][nt][0], c[mt][nt][1]);
                uint32_t h23 = pack_f16x2(c[mt][nt][2], c[mt][nt][3]);
                if (row0 < M) *(uint32_t*)(Ch + (size_t)row0 * N + col) = h01;
                if (row0 + 8 < M) *(uint32_t*)(Ch + (size_t)(row0 + 8) * N + col) = h23;
            } else {
                float* C = (float*)Cv;
                float b0 = bias ? bias[col] : 0.f;
                float b1 = bias ? bias[col + 1] : 0.f;
                if (row0 < M)
                    *(float2*)(C + (size_t)row0 * N + col) =
                        make_float2(c[mt][nt][0] + b0, c[mt][nt][1] + b1);
                if (row0 + 8 < M)
                    *(float2*)(C + (size_t)(row0 + 8) * N + col) =
                        make_float2(c[mt][nt][2] + b0, c[mt][nt][3] + b1);
            }
        }
    }
}

// ---------------- fused s=2 + s=4 mean pooling ----------------------------------
__global__ void pool_both(const __half* __restrict__ lat,
                          __half* __restrict__ lp2, __half* __restrict__ lp4) {
    const int N2 = Bv * 144 * LDv;
    const int N4 = Bv * 36 * LDv;
    int idx = blockIdx.x * blockDim.x + threadIdx.x;
    if (idx < N2) {
        int c = idx & (LDv - 1);
        int rest = idx >> 8;
        int cell = rest % 144;
        int b = rest / 144;
        int gh = cell / 12, gw = cell % 12;
        float sum = 0.f;
        for (int i = 0; i < 2; i++)
            for (int j = 0; j < 2; j++)
                sum += __half2float(
                    lat[((size_t)(b * Tv) + (gh * 2 + i) * 24 + (gw * 2 + j)) * LDv + c]);
        lp2[idx] = __float2half(sum * 0.25f);
    } else if (idx < N2 + N4) {
        int k = idx - N2;
        int c = k & (LDv - 1);
        int rest = k >> 8;
        int cell = rest % 36;
        int b = rest / 36;
        int gh = cell / 6, gw = cell % 6;
        float sum = 0.f;
        for (int i = 0; i < 4; i++)
            for (int j = 0; j < 4; j++)
                sum += __half2float(
                    lat[((size_t)(b * Tv) + (gh * 4 + i) * 24 + (gw * 4 + j)) * LDv + c]);
        lp4[k] = __float2half(sum * 0.0625f);
    }
}

// ---------------- fused 3-scale fp16 flash attention ---------------------------
// s=1 fast path (separable integer bias); exp via ex2.approx.f16x2;
// cross-segment ctx accumulation kept in REGISTERS (oa), single fp16 store.
#define ATT_SMEM_WORDS 14080

__global__ __launch_bounds__(256, 2) void attn_fused(
    const __half* __restrict__ qbuf,
    const __half* __restrict__ k1, const __half* __restrict__ v1,
    const __half* __restrict__ k2, const __half* __restrict__ v2,
    const __half* __restrict__ k4, const __half* __restrict__ v4,
    const float* __restrict__ t2e, __half* __restrict__ ctxh) {
    extern __shared__ uint32_t smu[];
    float* khcs = (float*)(smu + 13824);
    float* kwcs = khcs + 128;
    int* ibase = (int*)khcs;
    uint32_t sb = (uint32_t)__cvta_generic_to_shared(smu);

    const int b = blockIdx.z;
    const int h = blockIdx.y;
    const int q0 = blockIdx.x * 128;
    const int tid = threadIdx.x;
    const int lane = tid & 31;
    const int w = tid >> 5;
    const int g = lane >> 2;
    const int t = lane & 3;
    const int lr0 = w * 16 + g;
    const int lr1 = lr0 + 8;

    auto issue_kv = [&](int vt) {
        const __half *kb, *vb;
        int Kt, kt;
        if (vt < 9) {
            kb = k1 + (size_t)b * 576 * DMv + h * HDv;
            vb = v1 + (size_t)b * 576 * DMv + h * HDv;
            Kt = 576; kt = vt;
        } else if (vt < 12) {
            kb = k2 + (size_t)b * 144 * DMv + h * HDv;
            vb = v2 + (size_t)b * 144 * DMv + h * HDv;
            Kt = 144; kt = vt - 9;
        } else {
            kb = k4 + (size_t)b * 36 * DMv + h * HDv;
            vb = v4 + (size_t)b * 36 * DMv + h * HDv;
            Kt = 36; kt = 0;
        }
        int buf = vt & 1;
#pragma unroll
        for (int u = 0; u < 2; u++) {
            int idx = u * 256 + tid;
            int r = idx >> 3;
            int c8 = (idx & 7) << 3;
            int kg = kt * 64 + r;
            int pred = kg < Kt;
            cpa16z(sb + (buf * 2304 + r * 36 + (c8 >> 1)) * 4,
                   kb + (size_t)kg * DMv + c8, pred);
            cpa16z(sb + (4608 + buf * 2304 + r * 36 + (c8 >> 1)) * 4,
                   vb + (size_t)kg * DMv + c8, pred);
        }
    };

    const __half* qsrc = qbuf + (size_t)(b * Tv) * DMv + h * HDv;
#pragma unroll
    for (int u = 0; u < 4; u++) {
        int idx = u * 256 + tid;
        int r = idx >> 3;
        int c8 = (idx & 7) << 3;
        int row = q0 + r;
        if (row > Tv - 1) row = Tv - 1;
        *(uint4*)&smu[9216 + r * 36 + (c8 >> 1)] =
            *(const uint4*)(qsrc + (size_t)row * DMv + c8);
    }
    issue_kv(0);
    cp_commit();
    __syncthreads();

    uint32_t qf[4][4];
#pragma unroll
    for (int ks = 0; ks < 4; ks++) {
        qf[ks][0] = smu[9216 + lr0 * 36 + ks * 8 + t];
        qf[ks][1] = smu[9216 + lr1 * 36 + ks * 8 + t];
        qf[ks][2] = smu[9216 + lr0 * 36 + ks * 8 + t + 4];
        qf[ks][3] = smu[9216 + lr1 * 36 + ks * 8 + t + 4];
    }

    float o[8][4], oa[8][4];
#pragma unroll
    for (int nt = 0; nt < 8; nt++)
#pragma unroll
        for (int r = 0; r < 4; r++) { o[nt][r] = 0.f; oa[nt][r] = 0.f; }
    float l0 = 0.f, l1 = 0.f;

    const float scl = 0.125f * LOG2E;
    const int qi0 = q0 + lr0;
    const int qi1 = q0 + lr1;
    const int qc0 = qi0 < Tv ? qi0 : Tv - 1;
    const int qc1 = qi1 < Tv ? qi1 : Tv - 1;
    const int qh0i = qc0 / 24, qw0i = qc0 % 24;
    const int qh1i = qc1 / 24, qw1i = qc1 % 24;
    const int qoff0 = qh0i * 47 + qw0i;
    const int qoff1 = qh1i * 47 + qw1i;
    const float qh0 = (float)qh0i, qw0 = (float)qw0i;
    const float qh1 = (float)qh1i, qw1 = (float)qw1i;
    __half* c0ph = ctxh + ((size_t)(b * Tv + qc0)) * DMv + h * HDv;
    __half* c1ph = ctxh + ((size_t)(b * Tv + qc1)) * DMv + h * HDv;

    const uint32_t krow = sb + (((lane & 7) * 36) + ((lane >> 3) << 2)) * 4;
    const uint32_t vrow = sb + 4608 * 4 +
        (((((lane >> 3) & 1) * 8 + (lane & 7)) * 36) + ((lane >> 4) << 2)) * 4;

    for (int vt = 0; vt < 13; vt++) {
        int Kt, kt, gw_, s_, tw_;
        const float* tb;
        if (vt < 9)       { Kt = 576; kt = vt;      gw_ = 24; s_ = 1; tw_ = 47; tb = t2e + T2E_1 + h * (47 * 47); }
        else if (vt < 12) { Kt = 144; kt = vt - 9;  gw_ = 12; s_ = 2; tw_ = 23; tb = t2e + T2E_2 + h * (47 * 23); }
        else              { Kt = 36;  kt = 0;       gw_ = 6;  s_ = 4; tw_ = 11; tb = t2e + T2E_4 + h * (47 * 11); }
        const float hctr = 0.5f * (float)(s_ - 1);
        const int buf = vt & 1;

        cp_wait0();
        if (tid < 64) {
            int kg = kt * 64 + tid;
            if (vt < 9) {
                ibase[buf * 64 + tid] = (23 - kg / 24) * 47 + (23 - kg % 24);
            } else if (kg < Kt) {
                khcs[buf * 64 + tid] = (float)((kg / gw_) * s_) + hctr;
                kwcs[buf * 64 + tid] = (float)((kg % gw_) * s_) + hctr;
            }
        }
        __syncthreads();
        if (vt + 1 < 13) { issue_kv(vt + 1); cp_commit(); }

        const uint32_t kbase = krow + (buf * 2304) * 4;
        const uint32_t vbase = vrow + (buf * 2304) * 4;

        uint32_t pA[8], pB[8];
        if (vt < 9) {
            const int* ib = ibase + buf * 64;
#pragma unroll
            for (int nt = 0; nt < 8; nt++) {
                uint32_t r0, r1, r2, r3, r4, r5, r6, r7;
                ldsm4(r0, r1, r2, r3, kbase + (nt * 8 * 36) * 4);
                ldsm4(r4, r5, r6, r7, kbase + (nt * 8 * 36) * 4 + 64);
                float s0 = 0.f, s1 = 0.f, s2 = 0.f, s3 = 0.f;
                mma_f16(s0, s1, s2, s3, qf[0][0], qf[0][1], qf[0][2], qf[0][3], r0, r1);
                mma_f16(s0, s1, s2, s3, qf[1][0], qf[1][1], qf[1][2], qf[1][3], r2, r3);
                mma_f16(s0, s1, s2, s3, qf[2][0], qf[2][1], qf[2][2], qf[2][3], r4, r5);
                mma_f16(s0, s1, s2, s3, qf[3][0], qf[3][1], qf[3][2], qf[3][3], r6, r7);

                int lc = nt * 8 + t * 2;
                int bA = ib[lc], bB2 = ib[lc + 1];
                float x0 = s0 * scl + __ldg(tb + bA + qoff0);
                float x1 = s1 * scl + __ldg(tb + bB2 + qoff0);
                float x2 = s2 * scl + __ldg(tb + bA + qoff1);
                float x3 = s3 * scl + __ldg(tb + bB2 + qoff1);
                uint32_t eA = ex2_f16x2(pack_f16x2(x0, x1));
                uint32_t eB = ex2_f16x2(pack_f16x2(x2, x3));
                float2 fA = __half22float2(*(__half2*)&eA);
                float2 fB = __half22float2(*(__half2*)&eB);
                l0 += fA.x + fA.y;
                l1 += fB.x + fB.y;
                pA[nt] = eA;
                pB[nt] = eB;
            }
        } else {
#pragma unroll
            for (int nt = 0; nt < 8; nt++) {
                uint32_t r0, r1, r2, r3, r4, r5, r6, r7;
                ldsm4(r0, r1, r2, r3, kbase + (nt * 8 * 36) * 4);
                ldsm4(r4, r5, r6, r7, kbase + (nt * 8 * 36) * 4 + 64);
                float s0 = 0.f, s1 = 0.f, s2 = 0.f, s3 = 0.f;
                mma_f16(s0, s1, s2, s3, qf[0][0], qf[0][1], qf[0][2], qf[0][3], r0, r1);
                mma_f16(s0, s1, s2, s3, qf[1][0], qf[1][1], qf[1][2], qf[1][3], r2, r3);
                mma_f16(s0, s1, s2, s3, qf[2][0], qf[2][1], qf[2][2], qf[2][3], r4, r5);
                mma_f16(s0, s1, s2, s3, qf[3][0], qf[3][1], qf[3][2], qf[3][3], r6, r7);

                int lc = nt * 8 + t * 2;
                int kg = kt * 64 + lc;
                if (kg < Kt) {
                    float khcA = khcs[buf * 64 + lc], kwcA = kwcs[buf * 64 + lc];
                    float khcB = khcs[buf * 64 + lc + 1], kwcB = kwcs[buf * 64 + lc + 1];
                    int rh0a = (int)(qh0 - khcA) + 23, rw0a = (int)(qw0 - kwcA) + (gw_ - 1);
                    int rh0b = (int)(qh0 - khcB) + 23, rw0b = (int)(qw0 - kwcB) + (gw_ - 1);
                    int rh1a = (int)(qh1 - khcA) + 23, rw1a = (int)(qw1 - kwcA) + (gw_ - 1);
                    int rh1b = (int)(qh1 - khcB) + 23, rw1b = (int)(qw1 - kwcB) + (gw_ - 1);
                    float x0 = s0 * scl + __ldg(&tb[rh0a * tw_ + rw0a]);
                    float x1 = s1 * scl + __ldg(&tb[rh0b * tw_ + rw0b]);
                    float x2 = s2 * scl + __ldg(&tb[rh1a * tw_ + rw1a]);
                    float x3 = s3 * scl + __ldg(&tb[rh1b * tw_ + rw1b]);
                    uint32_t eA = ex2_f16x2(pack_f16x2(x0, x1));
                    uint32_t eB = ex2_f16x2(pack_f16x2(x2, x3));
                    float2 fA = __half22float2(*(__half2*)&eA);
                    float2 fB = __half22float2(*(__half2*)&eB);
                    l0 += fA.x + fA.y;
                    l1 += fB.x + fB.y;
                    pA[nt] = eA;
                    pB[nt] = eB;
                } else {
                    pA[nt] = 0u;
                    pB[nt] = 0u;
                }
            }
        }

#pragma unroll
        for (int ks = 0; ks < 4; ks++) {
            uint32_t a0 = pA[2 * ks], a1 = pB[2 * ks];
            uint32_t a2 = pA[2 * ks + 1], a3 = pB[2 * ks + 1];
#pragma unroll
            for (int p = 0; p < 4; p++) {
                uint32_t v0, v1, v2, v3;
                ldsm4t(v0, v1, v2, v3, vbase + (ks * 16 * 36 + p * 8) * 4);
                mma_f16(o[2 * p][0], o[2 * p][1], o[2 * p][2], o[2 * p][3],
                        a0, a1, a2, a3, v0, v1);
                mma_f16(o[2 * p + 1][0], o[2 * p + 1][1], o[2 * p + 1][2], o[2 * p + 1][3],
                        a0, a1, a2, a3, v2, v3);
            }
        }

        if (vt == 8 || vt == 11 || vt == 12) {
            float L0 = l0, L1 = l1;
            L0 += __shfl_xor_sync(0xffffffffu, L0, 1);
            L0 += __shfl_xor_sync(0xffffffffu, L0, 2);
            L1 += __shfl_xor_sync(0xffffffffu, L1, 1);
            L1 += __shfl_xor_sync(0xffffffffu, L1, 2);
            float inv0 = 1.f / (3.f * L0);
            float inv1 = 1.f / (3.f * L1);
            // accumulate normalized segment output in registers
#pragma unroll
            for (int nt = 0; nt < 8; nt++) {
                oa[nt][0] += o[nt][0] * inv0;
                oa[nt][1] += o[nt][1] * inv0;
                oa[nt][2] += o[nt][2] * inv1;
                oa[nt][3] += o[nt][3] * inv1;
                o[nt][0] = 0.f; o[nt][1] = 0.f; o[nt][2] = 0.f; o[nt][3] = 0.f;
            }
            l0 = 0.f;
            l1 = 0.f;
            if (vt == 12) {
                // single fp16 store of the fully accumulated ctx
#pragma unroll
                for (int nt = 0; nt < 8; nt++) {
                    int col = nt * 8 + t * 2;
                    if (qi0 < Tv)
                        *(uint32_t*)(c0ph + col) = pack_f16x2(oa[nt][0], oa[nt][1]);
                    if (qi1 < Tv)
                        *(uint32_t*)(c1ph + col) = pack_f16x2(oa[nt][2], oa[nt][3]);
                }
            }
        }
    }
}

// ---------------- launch ------------------------------------------------------
extern "C" void kernel_launch(void* const* d_in, const int* in_sizes, int n_in,
                              void* d_out, int out_size) {
    const float* x    = (const float*)d_in[0];
    const float* wq   = (const float*)d_in[1];
    const float* wdkv = (const float*)d_in[2];
    const float* wuk1 = (const float*)d_in[3];
    const float* wuk2 = (const float*)d_in[4];
    const float* wuk4 = (const float*)d_in[5];
    const float* wuv1 = (const float*)d_in[6];
    const float* wuv2 = (const float*)d_in[7];
    const float* wuv4 = (const float*)d_in[8];
    const float* wout = (const float*)d_in[9];
    const float* bout = (const float*)d_in[10];
    const float* tbl1 = (const float*)d_in[11];
    const float* tbl2 = (const float*)d_in[12];
    const float* tbl4 = (const float*)d_in[13];

    float* t2e;
    __half *qh, *lath, *lp2h, *lp4h, *kh, *vh, *k2h, *v2h, *k4h, *v4h, *wch, *xh, *ctxh;
    cudaGetSymbolAddress((void**)&qh, g_qh);
    cudaGetSymbolAddress((void**)&lath, g_lath);
    cudaGetSymbolAddress((void**)&lp2h, g_lp2h);
    cudaGetSymbolAddress((void**)&lp4h, g_lp4h);
    cudaGetSymbolAddress((void**)&kh, g_kh);
    cudaGetSymbolAddress((void**)&vh, g_vh);
    cudaGetSymbolAddress((void**)&k2h, g_k2h);
    cudaGetSymbolAddress((void**)&v2h, g_v2h);
    cudaGetSymbolAddress((void**)&k4h, g_k4h);
    cudaGetSymbolAddress((void**)&v4h, g_v4h);
    cudaGetSymbolAddress((void**)&ctxh, g_ctxh);
    cudaGetSymbolAddress((void**)&wch, g_wch);
    cudaGetSymbolAddress((void**)&xh, g_xh);
    cudaGetSymbolAddress((void**)&t2e, g_t2e);

    const int O_WQ = 0, O_WDKV = 589824, O_WUK1 = 786432, O_WUV1 = 983040;
    const int O_WUK2 = 1179648, O_WUV2 = 1376256, O_WUK4 = 1572864, O_WUV4 = 1769472;
    const int O_WOUT = 1966080;

    CvtArgs ca;
    ca.src[0] = wq;   ca.dst[0] = wch + O_WQ;   ca.n4[0] = 589824 / 4;
    ca.src[1] = wdkv; ca.dst[1] = wch + O_WDKV; ca.n4[1] = 196608 / 4;
    ca.src[2] = wuk1; ca.dst[2] = wch + O_WUK1; ca.n4[2] = 196608 / 4;
    ca.src[3] = wuv1; ca.dst[3] = wch + O_WUV1; ca.n4[3] = 196608 / 4;
    ca.src[4] = wuk2; ca.dst[4] = wch + O_WUK2; ca.n4[4] = 196608 / 4;
    ca.src[5] = wuv2; ca.dst[5] = wch + O_WUV2; ca.n4[5] = 196608 / 4;
    ca.src[6] = wuk4; ca.dst[6] = wch + O_WUK4; ca.n4[6] = 196608 / 4;
    ca.src[7] = wuv4; ca.dst[7] = wch + O_WUV4; ca.n4[7] = 196608 / 4;
    ca.src[8] = wout; ca.dst[8] = wch + O_WOUT; ca.n4[8] = 589824 / 4;
    ca.src[9] = x;    ca.dst[9] = xh;           ca.n4[9] = Bv * Tv * DMv / 4;
    ca.t1 = tbl1; ca.t2 = tbl2; ca.t4 = tbl4; ca.t2e = t2e;

    const int GEMM_SMEM = 26880 * 4;           // 107,520 B
    const int ATT_SMEM = ATT_SMEM_WORDS * 4;   // 56,320 B
    cudaFuncSetAttribute(gemm_fp16, cudaFuncAttributeMaxDynamicSharedMemorySize,
                         GEMM_SMEM);
    cudaFuncSetAttribute(attn_fused, cudaFuncAttributeMaxDynamicSharedMemorySize,
                         ATT_SMEM);

    const int MQ = Bv * Tv;  // 9216

    cvtw_kernel<<<512, 256>>>(ca);

    // ---- QL: q-proj (x<6) + lat-proj (x>=6), K=768 ----
    GemmJobs jql = {};
    jql.A[0] = xh;  jql.B[0] = wch + O_WQ;   jql.C[0] = qh;
    jql.M[0] = MQ;  jql.N[0] = DMv;          jql.fp16out[0] = 1;
    jql.A[1] = xh;  jql.B[1] = wch + O_WDKV; jql.C[1] = lath;
    jql.M[1] = MQ;  jql.N[1] = LDv;          jql.fp16out[1] = 1;
    gemm_fp16<<<dim3(8, 72, 1), 256, GEMM_SMEM>>>(jql, nullptr, DMv, 6);

    pool_both<<<(Bv * 180 * LDv + 255) / 256, 256>>>(lath, lp2h, lp4h);

    // ---- KV: all six k/v up-projections, K=256 ----
    GemmJobs jkv = {};
    jkv.A[0] = lath; jkv.B[0] = wch + O_WUK1; jkv.C[0] = kh;  jkv.M[0] = MQ;
    jkv.A[1] = lath; jkv.B[1] = wch + O_WUV1; jkv.C[1] = vh;  jkv.M[1] = MQ;
    jkv.A[2] = lp2h; jkv.B[2] = wch + O_WUK2; jkv.C[2] = k2h; jkv.M[2] = Bv * 144;
    jkv.A[3] = lp2h; jkv.B[3] = wch + O_WUV2; jkv.C[3] = v2h; jkv.M[3] = Bv * 144;
    jkv.A[4] = lp4h; jkv.B[4] = wch + O_WUK4; jkv.C[4] = k4h; jkv.M[4] = Bv * 36;
    jkv.A[5] = lp4h; jkv.B[5] = wch + O_WUV4; jkv.C[5] = v4h; jkv.M[5] = Bv * 36;
    for (int j = 0; j < 6; j++) { jkv.N[j] = DMv; jkv.fp16out[j] = 1; }
    gemm_fp16<<<dim3(6, 72, 6), 256, GEMM_SMEM>>>(jkv, nullptr, LDv, 6);

    attn_fused<<<dim3(5, NHv, Bv), 256, ATT_SMEM>>>(qh, kh, vh, k2h, v2h, k4h, v4h,
                                                    t2e, ctxh);

    // ---- OUT: out-projection, fp32 + bias ----
    GemmJobs jo = {};
    jo.A[0] = ctxh; jo.B[0] = wch + O_WOUT; jo.C[0] = d_out;
    jo.M[0] = MQ;   jo.N[0] = DMv;          jo.fp16out[0] = 0;
    jo.A[1] = ctxh; jo.B[1] = wch + O_WOUT; jo.C[1] = d_out;
    jo.M[1] = MQ;   jo.N[1] = DMv;          jo.fp16out[1] = 0;
    gemm_fp16<<<dim3(6, 72, 1), 256, GEMM_SMEM>>>(jo, bout, DMv, 6);
}

// round 16
// speedup vs baseline: 1.2613x; 1.0152x over previous
#include <cuda_runtime.h>
#include <cuda_fp16.h>
#include <cstdint>
#include <cstddef>

#define Bv 16
#define Tv 576
#define NHv 12
#define HDv 64
#define DMv 768
#define LDv 256

// ---------------- scratch (static device allocations; no cudaMalloc) ---------
__device__ __half g_qh[Bv * Tv * DMv];
__device__ __half g_lath[Bv * Tv * LDv];
__device__ __half g_lp2h[Bv * 144 * LDv];
__device__ __half g_lp4h[Bv * 36 * LDv];
__device__ __half g_kh[Bv * Tv * DMv];
__device__ __half g_vh[Bv * Tv * DMv];
__device__ __half g_k2h[Bv * 144 * DMv];
__device__ __half g_v2h[Bv * 144 * DMv];
__device__ __half g_k4h[Bv * 36 * DMv];
__device__ __half g_v4h[Bv * 36 * DMv];
__device__ __half g_ctxh[Bv * Tv * DMv];
__device__ __half g_wch[2555904];        // fp16 weights
__device__ __half g_xh[Bv * Tv * DMv];   // fp16 x
__device__ float g_t2e[45684];           // bias tables * log2(e)

#define T2E_1 0
#define T2E_2 26508
#define T2E_4 39480
#define LOG2E 1.4426950408889634f

// ---------------- helpers -----------------------------------------------------
__device__ __forceinline__ uint32_t pack_f16x2(float lo, float hi) {
    uint32_t u;
    asm("cvt.rn.f16x2.f32 %0, %1, %2;" : "=r"(u) : "f"(hi), "f"(lo));
    return u;
}
__device__ __forceinline__ uint32_t ex2_f16x2(uint32_t x) {
    uint32_t r;
    asm("ex2.approx.f16x2 %0, %1;" : "=r"(r) : "r"(x));
    return r;
}

__device__ __forceinline__ void mma_f16(float& c0, float& c1, float& c2, float& c3,
                                        uint32_t a0, uint32_t a1, uint32_t a2, uint32_t a3,
                                        uint32_t b0, uint32_t b1) {
    asm volatile(
        "mma.sync.aligned.m16n8k16.row.col.f32.f16.f16.f32 "
        "{%0,%1,%2,%3}, {%4,%5,%6,%7}, {%8,%9}, {%0,%1,%2,%3};"
        : "+f"(c0), "+f"(c1), "+f"(c2), "+f"(c3)
        : "r"(a0), "r"(a1), "r"(a2), "r"(a3), "r"(b0), "r"(b1));
}

__device__ __forceinline__ void ldsm4(uint32_t& r0, uint32_t& r1, uint32_t& r2,
                                      uint32_t& r3, uint32_t addr) {
    asm volatile("ldmatrix.sync.aligned.m8n8.x4.shared.b16 {%0,%1,%2,%3}, [%4];"
                 : "=r"(r0), "=r"(r1), "=r"(r2), "=r"(r3) : "r"(addr));
}
__device__ __forceinline__ void ldsm4t(uint32_t& r0, uint32_t& r1, uint32_t& r2,
                                       uint32_t& r3, uint32_t addr) {
    asm volatile("ldmatrix.sync.aligned.m8n8.x4.trans.shared.b16 {%0,%1,%2,%3}, [%4];"
                 : "=r"(r0), "=r"(r1), "=r"(r2), "=r"(r3) : "r"(addr));
}

__device__ __forceinline__ void cpa16(uint32_t dst, const void* src) {
    asm volatile("cp.async.cg.shared.global [%0], [%1], 16;" :: "r"(dst), "l"(src));
}
__device__ __forceinline__ void cpa16z(uint32_t dst, const void* src, int pred) {
    asm volatile(
        "{\n\t.reg .pred p;\n\tsetp.ne.b32 p, %2, 0;\n\t"
        "@p cp.async.cg.shared.global [%0], [%1], 16;\n\t"
        "@!p cp.async.cg.shared.global [%0], [%1], 16, 0;\n\t}"
        :: "r"(dst), "l"(src), "r"(pred));
}
__device__ __forceinline__ void cp_commit() { asm volatile("cp.async.commit_group;"); }
__device__ __forceinline__ void cp_wait0() { asm volatile("cp.async.wait_group 0;"); }
__device__ __forceinline__ void cp_wait1() { asm volatile("cp.async.wait_group 1;"); }

// ---------------- fp16 pre-conversion + bias-table scaling, one kernel ---------
struct CvtArgs {
    const float* src[10];
    __half* dst[10];
    int n4[10];
    const float* t1;
    const float* t2;
    const float* t4;
    float* t2e;
};
__global__ void cvtw_kernel(CvtArgs a) {
    int gid = blockIdx.x * blockDim.x + threadIdx.x;
    int stride = gridDim.x * blockDim.x;
#pragma unroll
    for (int s = 0; s < 10; s++) {
        const float4* sp = (const float4*)a.src[s];
        uint2* dp = (uint2*)a.dst[s];
        int n = a.n4[s];
        for (int i = gid; i < n; i += stride) {
            float4 v = sp[i];
            uint2 o;
            o.x = pack_f16x2(v.x, v.y);
            o.y = pack_f16x2(v.z, v.w);
            dp[i] = o;
        }
    }
    for (int i = gid; i < 26508; i += stride) a.t2e[T2E_1 + i] = a.t1[i] * LOG2E;
    for (int i = gid; i < 12972; i += stride) a.t2e[T2E_2 + i] = a.t2[i] * LOG2E;
    for (int i = gid; i < 6204; i += stride)  a.t2e[T2E_4 + i] = a.t4[i] * LOG2E;
}

// ---------------- fp16 tensor-core GEMM, multi-job, 3-stage, 128x128, BK=64 ----
struct GemmJobs {
    const __half* A[6];
    const __half* B[6];
    void* C[6];
    int M[6];
    int N[6];
    int fp16out[6];
};

__global__ __launch_bounds__(256, 2) void gemm_fp16(
    GemmJobs J, const float* __restrict__ bias, int K, int xsplit) {
    int job, bnIdx;
    if (gridDim.z > 1) {
        job = blockIdx.z;
        bnIdx = blockIdx.x;
    } else {
        job = (blockIdx.x >= xsplit) ? 1 : 0;
        bnIdx = job ? (blockIdx.x - xsplit) : blockIdx.x;
    }
    const __half* A = J.A[job];
    const __half* Bw = J.B[job];
    void* Cv = J.C[job];
    const int M = J.M[job];
    const int N = J.N[job];
    const int fp16out = J.fp16out[job];

    const int bm = blockIdx.y * 128;
    if (bm >= M) return;
    const int bn = bnIdx * 128;

    extern __shared__ uint32_t sm[];
    const int tid = threadIdx.x;
    const int lane = tid & 31;
    const int warp = tid >> 5;
    const int wm = (warp & 1) * 64;
    const int wn = (warp >> 1) * 32;
    const int g = lane >> 2;
    const int t = lane & 3;
    const int nk = K >> 6;
    uint32_t sb = (uint32_t)__cvta_generic_to_shared(sm);

    auto issue = [&](int it) {
        int buf = it % 3;
        int k0 = it << 6;
#pragma unroll
        for (int u = 0; u < 4; u++) {
            int idx = u * 256 + tid;
            int r = idx >> 3;
            int ch = idx & 7;
            int pred = (bm + r) < M;
            cpa16z(sb + (buf * 4608 + r * 36 + ch * 4) * 4,
                   A + (size_t)(bm + r) * K + k0 + ch * 8, pred);
        }
#pragma unroll
        for (int u = 0; u < 4; u++) {
            int idx = u * 256 + tid;
            int kk = idx >> 4;
            int ch = idx & 15;
            cpa16(sb + (13824 + buf * 4352 + kk * 68 + ch * 4) * 4,
                  Bw + (size_t)(k0 + kk) * N + bn + ch * 8);
        }
        cp_commit();
    };

    float c[4][4][4];
#pragma unroll
    for (int mt = 0; mt < 4; mt++)
#pragma unroll
        for (int nt = 0; nt < 4; nt++)
#pragma unroll
            for (int r = 0; r < 4; r++) c[mt][nt][r] = 0.f;

    issue(0);
    issue(1);

    const uint32_t aB = sb + (((wm + (lane & 15)) * 36) + (lane >> 4) * 4) * 4;
    const uint32_t bB = sb + 13824 * 4 +
        (((((lane >> 3) & 1) * 8 + (lane & 7)) * 68) + (wn >> 1) + (lane >> 4) * 4) * 4;

    for (int it = 0; it < nk; it++) {
        if (it + 1 < nk) cp_wait1(); else cp_wait0();
        __syncthreads();
        if (it + 2 < nk) issue(it + 2);
        const uint32_t aOff = (uint32_t)((it % 3) * 4608 * 4);
        const uint32_t bOff = (uint32_t)((it % 3) * 4352 * 4);
#pragma unroll
        for (int ks = 0; ks < 4; ks++) {
            uint32_t af[4][4];
#pragma unroll
            for (int mt = 0; mt < 4; mt++)
                ldsm4(af[mt][0], af[mt][1], af[mt][2], af[mt][3],
                      aB + aOff + (uint32_t)((mt * 16 * 36 + ks * 8) * 4));
            uint32_t bf[4][2];
#pragma unroll
            for (int nh = 0; nh < 2; nh++) {
                uint32_t v0, v1, v2, v3;
                ldsm4t(v0, v1, v2, v3,
                       bB + bOff + (uint32_t)((ks * 16 * 68 + nh * 8) * 4));
                bf[nh * 2][0] = v0; bf[nh * 2][1] = v1;
                bf[nh * 2 + 1][0] = v2; bf[nh * 2 + 1][1] = v3;
            }
#pragma unroll
            for (int mt = 0; mt < 4; mt++)
#pragma unroll
                for (int nt = 0; nt < 4; nt++)
                    mma_f16(c[mt][nt][0], c[mt][nt][1], c[mt][nt][2], c[mt][nt][3],
                            af[mt][0], af[mt][1], af[mt][2], af[mt][3],
                            bf[nt][0], bf[nt][1]);
        }
        __syncthreads();
    }

#pragma unroll
    for (int mt = 0; mt < 4; mt++) {
#pragma unroll
        for (int nt = 0; nt < 4; nt++) {
            int row0 = bm + wm + mt * 16 + g;
            int col = bn + wn + nt * 8 + t * 2;
            if (fp16out) {
                __half* Ch = (__half*)Cv;
                uint32_t h01 = pack_f16x2(c[mt][nt][0], c[mt][nt][1]);
                uint32_t h23 = pack_f16x2(c[mt][nt][2], c[mt][nt][3]);
                if (row0 < M) *(uint32_t*)(Ch + (size_t)row0 * N + col) = h01;
                if (row0 + 8 < M) *(uint32_t*)(Ch + (size_t)(row0 + 8) * N + col) = h23;
            } else {
                float* C = (float*)Cv;
                float b0 = bias ? bias[col] : 0.f;
                float b1 = bias ? bias[col + 1] : 0.f;
                if (row0 < M)
                    *(float2*)(C + (size_t)row0 * N + col) =
                        make_float2(c[mt][nt][0] + b0, c[mt][nt][1] + b1);
                if (row0 + 8 < M)
                    *(float2*)(C + (size_t)(row0 + 8) * N + col) =
                        make_float2(c[mt][nt][2] + b0, c[mt][nt][3] + b1);
            }
        }
    }
}

// ---------------- fused s=2 + s=4 mean pooling ----------------------------------
__global__ void pool_both(const __half* __restrict__ lat,
                          __half* __restrict__ lp2, __half* __restrict__ lp4) {
    const int N2 = Bv * 144 * LDv;
    const int N4 = Bv * 36 * LDv;
    int idx = blockIdx.x * blockDim.x + threadIdx.x;
    if (idx < N2) {
        int c = idx & (LDv - 1);
        int rest = idx >> 8;
        int cell = rest % 144;
        int b = rest / 144;
        int gh = cell / 12, gw = cell % 12;
        float sum = 0.f;
        for (int i = 0; i < 2; i++)
            for (int j = 0; j < 2; j++)
                sum += __half2float(
                    lat[((size_t)(b * Tv) + (gh * 2 + i) * 24 + (gw * 2 + j)) * LDv + c]);
        lp2[idx] = __float2half(sum * 0.25f);
    } else if (idx < N2 + N4) {
        int k = idx - N2;
        int c = k & (LDv - 1);
        int rest = k >> 8;
        int cell = rest % 36;
        int b = rest / 36;
        int gh = cell / 6, gw = cell % 6;
        float sum = 0.f;
        for (int i = 0; i < 4; i++)
            for (int j = 0; j < 4; j++)
                sum += __half2float(
                    lat[((size_t)(b * Tv) + (gh * 4 + i) * 24 + (gw * 4 + j)) * LDv + c]);
        lp4[k] = __float2half(sum * 0.0625f);
    }
}

// ---------------- fused 3-scale fp16 flash attention ---------------------------
// s=1 fast path; ex2.approx.f16x2; register ctx accumulation; warps whose
// 16 q-rows are entirely out of range skip all compute (tail block x=4).
#define ATT_SMEM_WORDS 14080

__global__ __launch_bounds__(256, 2) void attn_fused(
    const __half* __restrict__ qbuf,
    const __half* __restrict__ k1, const __half* __restrict__ v1,
    const __half* __restrict__ k2, const __half* __restrict__ v2,
    const __half* __restrict__ k4, const __half* __restrict__ v4,
    const float* __restrict__ t2e, __half* __restrict__ ctxh) {
    extern __shared__ uint32_t smu[];
    float* khcs = (float*)(smu + 13824);
    float* kwcs = khcs + 128;
    int* ibase = (int*)khcs;
    uint32_t sb = (uint32_t)__cvta_generic_to_shared(smu);

    const int b = blockIdx.z;
    const int h = blockIdx.y;
    const int q0 = blockIdx.x * 128;
    const int tid = threadIdx.x;
    const int lane = tid & 31;
    const int w = tid >> 5;
    const int g = lane >> 2;
    const int t = lane & 3;
    const int lr0 = w * 16 + g;
    const int lr1 = lr0 + 8;
    const bool active = (q0 + w * 16) < Tv;   // whole-warp uniform

    auto issue_kv = [&](int vt) {
        const __half *kb, *vb;
        int Kt, kt;
        if (vt < 9) {
            kb = k1 + (size_t)b * 576 * DMv + h * HDv;
            vb = v1 + (size_t)b * 576 * DMv + h * HDv;
            Kt = 576; kt = vt;
        } else if (vt < 12) {
            kb = k2 + (size_t)b * 144 * DMv + h * HDv;
            vb = v2 + (size_t)b * 144 * DMv + h * HDv;
            Kt = 144; kt = vt - 9;
        } else {
            kb = k4 + (size_t)b * 36 * DMv + h * HDv;
            vb = v4 + (size_t)b * 36 * DMv + h * HDv;
            Kt = 36; kt = 0;
        }
        int buf = vt & 1;
#pragma unroll
        for (int u = 0; u < 2; u++) {
            int idx = u * 256 + tid;
            int r = idx >> 3;
            int c8 = (idx & 7) << 3;
            int kg = kt * 64 + r;
            int pred = kg < Kt;
            cpa16z(sb + (buf * 2304 + r * 36 + (c8 >> 1)) * 4,
                   kb + (size_t)kg * DMv + c8, pred);
            cpa16z(sb + (4608 + buf * 2304 + r * 36 + (c8 >> 1)) * 4,
                   vb + (size_t)kg * DMv + c8, pred);
        }
    };

    const __half* qsrc = qbuf + (size_t)(b * Tv) * DMv + h * HDv;
#pragma unroll
    for (int u = 0; u < 4; u++) {
        int idx = u * 256 + tid;
        int r = idx >> 3;
        int c8 = (idx & 7) << 3;
        int row = q0 + r;
        if (row > Tv - 1) row = Tv - 1;
        *(uint4*)&smu[9216 + r * 36 + (c8 >> 1)] =
            *(const uint4*)(qsrc + (size_t)row * DMv + c8);
    }
    issue_kv(0);
    cp_commit();
    __syncthreads();

    uint32_t qf[4][4];
#pragma unroll
    for (int ks = 0; ks < 4; ks++) {
        qf[ks][0] = smu[9216 + lr0 * 36 + ks * 8 + t];
        qf[ks][1] = smu[9216 + lr1 * 36 + ks * 8 + t];
        qf[ks][2] = smu[9216 + lr0 * 36 + ks * 8 + t + 4];
        qf[ks][3] = smu[9216 + lr1 * 36 + ks * 8 + t + 4];
    }

    float o[8][4], oa[8][4];
#pragma unroll
    for (int nt = 0; nt < 8; nt++)
#pragma unroll
        for (int r = 0; r < 4; r++) { o[nt][r] = 0.f; oa[nt][r] = 0.f; }
    float l0 = 0.f, l1 = 0.f;

    const float scl = 0.125f * LOG2E;
    const int qi0 = q0 + lr0;
    const int qi1 = q0 + lr1;
    const int qc0 = qi0 < Tv ? qi0 : Tv - 1;
    const int qc1 = qi1 < Tv ? qi1 : Tv - 1;
    const int qh0i = qc0 / 24, qw0i = qc0 % 24;
    const int qh1i = qc1 / 24, qw1i = qc1 % 24;
    const int qoff0 = qh0i * 47 + qw0i;
    const int qoff1 = qh1i * 47 + qw1i;
    const float qh0 = (float)qh0i, qw0 = (float)qw0i;
    const float qh1 = (float)qh1i, qw1 = (float)qw1i;
    __half* c0ph = ctxh + ((size_t)(b * Tv + qc0)) * DMv + h * HDv;
    __half* c1ph = ctxh + ((size_t)(b * Tv + qc1)) * DMv + h * HDv;

    const uint32_t krow = sb + (((lane & 7) * 36) + ((lane >> 3) << 2)) * 4;
    const uint32_t vrow = sb + 4608 * 4 +
        (((((lane >> 3) & 1) * 8 + (lane & 7)) * 36) + ((lane >> 4) << 2)) * 4;

    for (int vt = 0; vt < 13; vt++) {
        int Kt, kt, gw_, s_, tw_;
        const float* tb;
        if (vt < 9)       { Kt = 576; kt = vt;      gw_ = 24; s_ = 1; tw_ = 47; tb = t2e + T2E_1 + h * (47 * 47); }
        else if (vt < 12) { Kt = 144; kt = vt - 9;  gw_ = 12; s_ = 2; tw_ = 23; tb = t2e + T2E_2 + h * (47 * 23); }
        else              { Kt = 36;  kt = 0;       gw_ = 6;  s_ = 4; tw_ = 11; tb = t2e + T2E_4 + h * (47 * 11); }
        const float hctr = 0.5f * (float)(s_ - 1);
        const int buf = vt & 1;

        cp_wait0();
        if (tid < 64) {
            int kg = kt * 64 + tid;
            if (vt < 9) {
                ibase[buf * 64 + tid] = (23 - kg / 24) * 47 + (23 - kg % 24);
            } else if (kg < Kt) {
                khcs[buf * 64 + tid] = (float)((kg / gw_) * s_) + hctr;
                kwcs[buf * 64 + tid] = (float)((kg % gw_) * s_) + hctr;
            }
        }
        __syncthreads();
        if (vt + 1 < 13) { issue_kv(vt + 1); cp_commit(); }

        if (active) {
            const uint32_t kbase = krow + (buf * 2304) * 4;
            const uint32_t vbase = vrow + (buf * 2304) * 4;

            uint32_t pA[8], pB[8];
            if (vt < 9) {
                const int* ib = ibase + buf * 64;
#pragma unroll
                for (int nt = 0; nt < 8; nt++) {
                    uint32_t r0, r1, r2, r3, r4, r5, r6, r7;
                    ldsm4(r0, r1, r2, r3, kbase + (nt * 8 * 36) * 4);
                    ldsm4(r4, r5, r6, r7, kbase + (nt * 8 * 36) * 4 + 64);
                    float s0 = 0.f, s1 = 0.f, s2 = 0.f, s3 = 0.f;
                    mma_f16(s0, s1, s2, s3, qf[0][0], qf[0][1], qf[0][2], qf[0][3], r0, r1);
                    mma_f16(s0, s1, s2, s3, qf[1][0], qf[1][1], qf[1][2], qf[1][3], r2, r3);
                    mma_f16(s0, s1, s2, s3, qf[2][0], qf[2][1], qf[2][2], qf[2][3], r4, r5);
                    mma_f16(s0, s1, s2, s3, qf[3][0], qf[3][1], qf[3][2], qf[3][3], r6, r7);

                    int lc = nt * 8 + t * 2;
                    int bA = ib[lc], bB2 = ib[lc + 1];
                    float x0 = s0 * scl + __ldg(tb + bA + qoff0);
                    float x1 = s1 * scl + __ldg(tb + bB2 + qoff0);
                    float x2 = s2 * scl + __ldg(tb + bA + qoff1);
                    float x3 = s3 * scl + __ldg(tb + bB2 + qoff1);
                    uint32_t eA = ex2_f16x2(pack_f16x2(x0, x1));
                    uint32_t eB = ex2_f16x2(pack_f16x2(x2, x3));
                    float2 fA = __half22float2(*(__half2*)&eA);
                    float2 fB = __half22float2(*(__half2*)&eB);
                    l0 += fA.x + fA.y;
                    l1 += fB.x + fB.y;
                    pA[nt] = eA;
                    pB[nt] = eB;
                }
            } else {
#pragma unroll
                for (int nt = 0; nt < 8; nt++) {
                    uint32_t r0, r1, r2, r3, r4, r5, r6, r7;
                    ldsm4(r0, r1, r2, r3, kbase + (nt * 8 * 36) * 4);
                    ldsm4(r4, r5, r6, r7, kbase + (nt * 8 * 36) * 4 + 64);
                    float s0 = 0.f, s1 = 0.f, s2 = 0.f, s3 = 0.f;
                    mma_f16(s0, s1, s2, s3, qf[0][0], qf[0][1], qf[0][2], qf[0][3], r0, r1);
                    mma_f16(s0, s1, s2, s3, qf[1][0], qf[1][1], qf[1][2], qf[1][3], r2, r3);
                    mma_f16(s0, s1, s2, s3, qf[2][0], qf[2][1], qf[2][2], qf[2][3], r4, r5);
                    mma_f16(s0, s1, s2, s3, qf[3][0], qf[3][1], qf[3][2], qf[3][3], r6, r7);

                    int lc = nt * 8 + t * 2;
                    int kg = kt * 64 + lc;
                    if (kg < Kt) {
                        float khcA = khcs[buf * 64 + lc], kwcA = kwcs[buf * 64 + lc];
                        float khcB = khcs[buf * 64 + lc + 1], kwcB = kwcs[buf * 64 + lc + 1];
                        int rh0a = (int)(qh0 - khcA) + 23, rw0a = (int)(qw0 - kwcA) + (gw_ - 1);
                        int rh0b = (int)(qh0 - khcB) + 23, rw0b = (int)(qw0 - kwcB) + (gw_ - 1);
                        int rh1a = (int)(qh1 - khcA) + 23, rw1a = (int)(qw1 - kwcA) + (gw_ - 1);
                        int rh1b = (int)(qh1 - khcB) + 23, rw1b = (int)(qw1 - kwcB) + (gw_ - 1);
                        float x0 = s0 * scl + __ldg(&tb[rh0a * tw_ + rw0a]);
                        float x1 = s1 * scl + __ldg(&tb[rh0b * tw_ + rw0b]);
                        float x2 = s2 * scl + __ldg(&tb[rh1a * tw_ + rw1a]);
                        float x3 = s3 * scl + __ldg(&tb[rh1b * tw_ + rw1b]);
                        uint32_t eA = ex2_f16x2(pack_f16x2(x0, x1));
                        uint32_t eB = ex2_f16x2(pack_f16x2(x2, x3));
                        float2 fA = __half22float2(*(__half2*)&eA);
                        float2 fB = __half22float2(*(__half2*)&eB);
                        l0 += fA.x + fA.y;
                        l1 += fB.x + fB.y;
                        pA[nt] = eA;
                        pB[nt] = eB;
                    } else {
                        pA[nt] = 0u;
                        pB[nt] = 0u;
                    }
                }
            }

#pragma unroll
            for (int ks = 0; ks < 4; ks++) {
                uint32_t a0 = pA[2 * ks], a1 = pB[2 * ks];
                uint32_t a2 = pA[2 * ks + 1], a3 = pB[2 * ks + 1];
#pragma unroll
                for (int p = 0; p < 4; p++) {
                    uint32_t v0, v1, v2, v3;
                    ldsm4t(v0, v1, v2, v3, vbase + (ks * 16 * 36 + p * 8) * 4);
                    mma_f16(o[2 * p][0], o[2 * p][1], o[2 * p][2], o[2 * p][3],
                            a0, a1, a2, a3, v0, v1);
                    mma_f16(o[2 * p + 1][0], o[2 * p + 1][1], o[2 * p + 1][2], o[2 * p + 1][3],
                            a0, a1, a2, a3, v2, v3);
                }
            }

            if (vt == 8 || vt == 11 || vt == 12) {
                float L0 = l0, L1 = l1;
                L0 += __shfl_xor_sync(0xffffffffu, L0, 1);
                L0 += __shfl_xor_sync(0xffffffffu, L0, 2);
                L1 += __shfl_xor_sync(0xffffffffu, L1, 1);
                L1 += __shfl_xor_sync(0xffffffffu, L1, 2);
                float inv0 = 1.f / (3.f * L0);
                float inv1 = 1.f / (3.f * L1);
#pragma unroll
                for (int nt = 0; nt < 8; nt++) {
                    oa[nt][0] += o[nt][0] * inv0;
                    oa[nt][1] += o[nt][1] * inv0;
                    oa[nt][2] += o[nt][2] * inv1;
                    oa[nt][3] += o[nt][3] * inv1;
                    o[nt][0] = 0.f; o[nt][1] = 0.f; o[nt][2] = 0.f; o[nt][3] = 0.f;
                }
                l0 = 0.f;
                l1 = 0.f;
                if (vt == 12) {
#pragma unroll
                    for (int nt = 0; nt < 8; nt++) {
                        int col = nt * 8 + t * 2;
                        if (qi0 < Tv)
                            *(uint32_t*)(c0ph + col) = pack_f16x2(oa[nt][0], oa[nt][1]);
                        if (qi1 < Tv)
                            *(uint32_t*)(c1ph + col) = pack_f16x2(oa[nt][2], oa[nt][3]);
                    }
                }
            }
        }
    }
}

// ---------------- launch ------------------------------------------------------
extern "C" void kernel_launch(void* const* d_in, const int* in_sizes, int n_in,
                              void* d_out, int out_size) {
    const float* x    = (const float*)d_in[0];
    const float* wq   = (const float*)d_in[1];
    const float* wdkv = (const float*)d_in[2];
    const float* wuk1 = (const float*)d_in[3];
    const float* wuk2 = (const float*)d_in[4];
    const float* wuk4 = (const float*)d_in[5];
    const float* wuv1 = (const float*)d_in[6];
    const float* wuv2 = (const float*)d_in[7];
    const float* wuv4 = (const float*)d_in[8];
    const float* wout = (const float*)d_in[9];
    const float* bout = (const float*)d_in[10];
    const float* tbl1 = (const float*)d_in[11];
    const float* tbl2 = (const float*)d_in[12];
    const float* tbl4 = (const float*)d_in[13];

    float* t2e;
    __half *qh, *lath, *lp2h, *lp4h, *kh, *vh, *k2h, *v2h, *k4h, *v4h, *wch, *xh, *ctxh;
    cudaGetSymbolAddress((void**)&qh, g_qh);
    cudaGetSymbolAddress((void**)&lath, g_lath);
    cudaGetSymbolAddress((void**)&lp2h, g_lp2h);
    cudaGetSymbolAddress((void**)&lp4h, g_lp4h);
    cudaGetSymbolAddress((void**)&kh, g_kh);
    cudaGetSymbolAddress((void**)&vh, g_vh);
    cudaGetSymbolAddress((void**)&k2h, g_k2h);
    cudaGetSymbolAddress((void**)&v2h, g_v2h);
    cudaGetSymbolAddress((void**)&k4h, g_k4h);
    cudaGetSymbolAddress((void**)&v4h, g_v4h);
    cudaGetSymbolAddress((void**)&ctxh, g_ctxh);
    cudaGetSymbolAddress((void**)&wch, g_wch);
    cudaGetSymbolAddress((void**)&xh, g_xh);
    cudaGetSymbolAddress((void**)&t2e, g_t2e);

    const int O_WQ = 0, O_WDKV = 589824, O_WUK1 = 786432, O_WUV1 = 983040;
    const int O_WUK2 = 1179648, O_WUV2 = 1376256, O_WUK4 = 1572864, O_WUV4 = 1769472;
    const int O_WOUT = 1966080;

    CvtArgs ca;
    ca.src[0] = wq;   ca.dst[0] = wch + O_WQ;   ca.n4[0] = 589824 / 4;
    ca.src[1] = wdkv; ca.dst[1] = wch + O_WDKV; ca.n4[1] = 196608 / 4;
    ca.src[2] = wuk1; ca.dst[2] = wch + O_WUK1; ca.n4[2] = 196608 / 4;
    ca.src[3] = wuv1; ca.dst[3] = wch + O_WUV1; ca.n4[3] = 196608 / 4;
    ca.src[4] = wuk2; ca.dst[4] = wch + O_WUK2; ca.n4[4] = 196608 / 4;
    ca.src[5] = wuv2; ca.dst[5] = wch + O_WUV2; ca.n4[5] = 196608 / 4;
    ca.src[6] = wuk4; ca.dst[6] = wch + O_WUK4; ca.n4[6] = 196608 / 4;
    ca.src[7] = wuv4; ca.dst[7] = wch + O_WUV4; ca.n4[7] = 196608 / 4;
    ca.src[8] = wout; ca.dst[8] = wch + O_WOUT; ca.n4[8] = 589824 / 4;
    ca.src[9] = x;    ca.dst[9] = xh;           ca.n4[9] = Bv * Tv * DMv / 4;
    ca.t1 = tbl1; ca.t2 = tbl2; ca.t4 = tbl4; ca.t2e = t2e;

    const int GEMM_SMEM = 26880 * 4;           // 107,520 B
    const int ATT_SMEM = ATT_SMEM_WORDS * 4;   // 56,320 B
    cudaFuncSetAttribute(gemm_fp16, cudaFuncAttributeMaxDynamicSharedMemorySize,
                         GEMM_SMEM);
    cudaFuncSetAttribute(attn_fused, cudaFuncAttributeMaxDynamicSharedMemorySize,
                         ATT_SMEM);

    const int MQ = Bv * Tv;  // 9216

    cvtw_kernel<<<512, 256>>>(ca);

    // ---- QL: q-proj (x<6) + lat-proj (x>=6), K=768 ----
    GemmJobs jql = {};
    jql.A[0] = xh;  jql.B[0] = wch + O_WQ;   jql.C[0] = qh;
    jql.M[0] = MQ;  jql.N[0] = DMv;          jql.fp16out[0] = 1;
    jql.A[1] = xh;  jql.B[1] = wch + O_WDKV; jql.C[1] = lath;
    jql.M[1] = MQ;  jql.N[1] = LDv;          jql.fp16out[1] = 1;
    gemm_fp16<<<dim3(8, 72, 1), 256, GEMM_SMEM>>>(jql, nullptr, DMv, 6);

    pool_both<<<(Bv * 180 * LDv + 255) / 256, 256>>>(lath, lp2h, lp4h);

    // ---- KV: all six k/v up-projections, K=256 ----
    GemmJobs jkv = {};
    jkv.A[0] = lath; jkv.B[0] = wch + O_WUK1; jkv.C[0] = kh;  jkv.M[0] = MQ;
    jkv.A[1] = lath; jkv.B[1] = wch + O_WUV1; jkv.C[1] = vh;  jkv.M[1] = MQ;
    jkv.A[2] = lp2h; jkv.B[2] = wch + O_WUK2; jkv.C[2] = k2h; jkv.M[2] = Bv * 144;
    jkv.A[3] = lp2h; jkv.B[3] = wch + O_WUV2; jkv.C[3] = v2h; jkv.M[3] = Bv * 144;
    jkv.A[4] = lp4h; jkv.B[4] = wch + O_WUK4; jkv.C[4] = k4h; jkv.M[4] = Bv * 36;
    jkv.A[5] = lp4h; jkv.B[5] = wch + O_WUV4; jkv.C[5] = v4h; jkv.M[5] = Bv * 36;
    for (int j = 0; j < 6; j++) { jkv.N[j] = DMv; jkv.fp16out[j] = 1; }
    gemm_fp16<<<dim3(6, 72, 6), 256, GEMM_SMEM>>>(jkv, nullptr, LDv, 6);

    attn_fused<<<dim3(5, NHv, Bv), 256, ATT_SMEM>>>(qh, kh, vh, k2h, v2h, k4h, v4h,
                                                    t2e, ctxh);

    // ---- OUT: out-projection, fp32 + bias ----
    GemmJobs jo = {};
    jo.A[0] = ctxh; jo.B[0] = wch + O_WOUT; jo.C[0] = d_out;
    jo.M[0] = MQ;   jo.N[0] = DMv;          jo.fp16out[0] = 0;
    jo.A[1] = ctxh; jo.B[1] = wch + O_WOUT; jo.C[1] = d_out;
    jo.M[1] = MQ;   jo.N[1] = DMv;          jo.fp16out[1] = 0;
    gemm_fp16<<<dim3(6, 72, 1), 256, GEMM_SMEM>>>(jo, bout, DMv, 6);
}